// round 1
// baseline (speedup 1.0000x reference)
#include <cuda_runtime.h>
#include <cstdint>

#define T_LEN 8192
#define BATCH 2
#define CDIM 1024
#define NHEAD 16
#define HDIM 64
#define WINSZ 256
#define NW 32            // windows per batch
#define NWIN_TOT 64      // BATCH * NW
#define NTOK (BATCH * T_LEN)   // 16384

// ---------------- scratch (device globals; no allocation allowed) ----------
__device__ float g_Q[(size_t)NTOK * CDIM];
__device__ float g_K[(size_t)NTOK * CDIM];
__device__ float g_V[(size_t)NTOK * CDIM];
__device__ float g_AO[(size_t)NTOK * CDIM];
__device__ unsigned char g_attend[NWIN_TOT * 512];
__device__ int g_maskmode;   // 0 = uint8/bool, 1 = int32, 2 = float32

// ---------------- mask dtype detection -------------------------------------
// Reads first 4096 32-bit words (16KB) — safe for all candidate layouts since
// the smallest possible buffer (bool, 1B/elem, 16384 elems) is exactly 16KB.
__global__ void detect_mask(const unsigned int* __restrict__ m) {
    __shared__ int okf, oki;
    if (threadIdx.x == 0) { okf = 1; oki = 1; }
    __syncthreads();
    for (int i = threadIdx.x; i < 4096; i += blockDim.x) {
        unsigned int w = m[i];
        if (w != 0u && w != 0x3f800000u) okf = 0;
        if (w > 1u) oki = 0;
    }
    __syncthreads();
    if (threadIdx.x == 0) g_maskmode = okf ? 2 : (oki ? 1 : 0);
}

// ---------------- per-window attend mask (512 ctx keys per window) ---------
__global__ void build_attend(const void* __restrict__ pm) {
    int w = blockIdx.x;            // 0..63
    int b = w >> 5;
    int wi = w & 31;
    int j = threadIdx.x;           // 0..511
    int p = wi * WINSZ - 128 + j;  // ctx position in original sequence
    int attend = 1;                // out-of-range: padded, pk=False -> attend
    if ((unsigned)p < (unsigned)T_LEN) {
        int mm = g_maskmode;
        size_t im = (size_t)b * T_LEN + p;
        int v;
        if (mm == 0)      v = ((const unsigned char*)pm)[im] != 0;
        else if (mm == 1) v = ((const int*)pm)[im] != 0;
        else              v = ((const float*)pm)[im] != 0.0f;
        attend = !v;
    }
    __shared__ int allb;
    if (j == 0) allb = 1;
    __syncthreads();
    if (!attend) allb = 0;
    __syncthreads();
    // reference quirk: if every key attendable, mask key 0
    if (j == 0 && allb) attend = 0;
    g_attend[w * 512 + j] = (unsigned char)attend;
}

// ---------------- fp32 SGEMM: C[M,N] = A[M,K] @ W[N,K]^T + bias ------------
// 128x128 block tile, 8x8 per thread, BK=8, 256 threads.
__global__ void __launch_bounds__(256) sgemm_bias(
        const float* __restrict__ A, const float* __restrict__ W,
        const float* __restrict__ bias, float* __restrict__ C,
        int M, int N, int K) {
    __shared__ float As[8][128];
    __shared__ float Bs[8][128];
    int tid = threadIdx.x;
    int tx = tid & 15, ty = tid >> 4;
    int row0 = blockIdx.y * 128;
    int col0 = blockIdx.x * 128;
    int lRow = tid >> 1;
    int lC4 = (tid & 1) << 2;
    const float* Ap = A + (size_t)(row0 + lRow) * K + lC4;
    const float* Wp = W + (size_t)(col0 + lRow) * K + lC4;

    float acc[8][8];
#pragma unroll
    for (int i = 0; i < 8; i++)
#pragma unroll
        for (int j = 0; j < 8; j++) acc[i][j] = 0.0f;

    for (int k0 = 0; k0 < K; k0 += 8) {
        float4 av = *(const float4*)(Ap + k0);
        float4 wv = *(const float4*)(Wp + k0);
        As[lC4 + 0][lRow] = av.x; As[lC4 + 1][lRow] = av.y;
        As[lC4 + 2][lRow] = av.z; As[lC4 + 3][lRow] = av.w;
        Bs[lC4 + 0][lRow] = wv.x; Bs[lC4 + 1][lRow] = wv.y;
        Bs[lC4 + 2][lRow] = wv.z; Bs[lC4 + 3][lRow] = wv.w;
        __syncthreads();
#pragma unroll
        for (int kk = 0; kk < 8; kk++) {
            float4 a0 = *(const float4*)&As[kk][ty * 8];
            float4 a1 = *(const float4*)&As[kk][ty * 8 + 4];
            float4 b0 = *(const float4*)&Bs[kk][tx * 8];
            float4 b1 = *(const float4*)&Bs[kk][tx * 8 + 4];
            float a[8] = {a0.x, a0.y, a0.z, a0.w, a1.x, a1.y, a1.z, a1.w};
            float bb[8] = {b0.x, b0.y, b0.z, b0.w, b1.x, b1.y, b1.z, b1.w};
#pragma unroll
            for (int i = 0; i < 8; i++)
#pragma unroll
                for (int j = 0; j < 8; j++) acc[i][j] += a[i] * bb[j];
        }
        __syncthreads();
    }
#pragma unroll
    for (int i = 0; i < 8; i++) {
        size_t crow = (size_t)(row0 + ty * 8 + i) * N + col0 + tx * 8;
#pragma unroll
        for (int j = 0; j < 8; j += 4) {
            float4 o;
            o.x = acc[i][j + 0] + bias[col0 + tx * 8 + j + 0];
            o.y = acc[i][j + 1] + bias[col0 + tx * 8 + j + 1];
            o.z = acc[i][j + 2] + bias[col0 + tx * 8 + j + 2];
            o.w = acc[i][j + 3] + bias[col0 + tx * 8 + j + 3];
            *(float4*)(C + crow + j) = o;
        }
    }
}

// ---------------- in-place RoPE on Q and K ----------------------------------
// Each thread handles the (d, d+32) pair of one head of one token -> in-place safe.
__global__ void rope_kernel(float* __restrict__ Q, float* __restrict__ K,
                            const float* __restrict__ cosT,
                            const float* __restrict__ sinT) {
    int idx = blockIdx.x * blockDim.x + threadIdx.x;  // 0 .. NTOK*512-1
    float* P = blockIdx.y ? K : Q;
    int token = idx >> 9;
    int r = idx & 511;
    int h = r >> 5;
    int d = r & 31;
    int pos = token & (T_LEN - 1);
    size_t base = (size_t)token * CDIM + h * HDIM;
    float a = P[base + d];
    float b = P[base + d + 32];
    float c1 = cosT[pos * HDIM + d], s1 = sinT[pos * HDIM + d];
    float c2 = cosT[pos * HDIM + d + 32], s2 = sinT[pos * HDIM + d + 32];
    P[base + d]      = a * c1 - b * s1;   // q*cos + rot_half(q)*sin, d < 32
    P[base + d + 32] = b * c2 + a * s2;   // d >= 32 part
}

// ---------------- windowed attention (flash-style online softmax) ----------
// grid: 64 windows * 16 heads * 4 query-chunks = 4096 blocks, 64 threads.
// Each thread owns one query row (64-dim q and acc in registers).
__global__ void __launch_bounds__(64) attn_kernel(
        const float* __restrict__ Q, const float* __restrict__ K,
        const float* __restrict__ V, float* __restrict__ AO) {
    __shared__ float Ks[64][64];
    __shared__ float Vs[64][64];
    __shared__ unsigned char am[64];

    int bid = blockIdx.x;
    int qc = bid & 3;
    int h = (bid >> 2) & 15;
    int w = bid >> 6;          // 0..63
    int b = w >> 5;
    int wi = w & 31;
    int tid = threadIdx.x;

    size_t qtok = (size_t)b * T_LEN + wi * WINSZ + qc * 64 + tid;
    const float* qp = Q + qtok * CDIM + h * HDIM;
    float q[64];
#pragma unroll
    for (int i = 0; i < 16; i++) {
        float4 t4 = ((const float4*)qp)[i];
        q[4 * i + 0] = t4.x; q[4 * i + 1] = t4.y;
        q[4 * i + 2] = t4.z; q[4 * i + 3] = t4.w;
    }
    float m = -1e30f, l = 0.0f;
    float acc[64];
#pragma unroll
    for (int d = 0; d < 64; d++) acc[d] = 0.0f;

    for (int kc = 0; kc < 8; kc++) {
        int base_p = wi * WINSZ - 128 + kc * 64;
#pragma unroll
        for (int it = 0; it < 16; it++) {
            int f = tid + it * 64;
            int r = f >> 4;
            int c4 = (f & 15) << 2;
            int p = base_p + r;
            float4 kv = make_float4(0.f, 0.f, 0.f, 0.f);
            float4 vv = make_float4(0.f, 0.f, 0.f, 0.f);
            if ((unsigned)p < (unsigned)T_LEN) {
                size_t tok = (size_t)b * T_LEN + p;
                kv = *(const float4*)(K + tok * CDIM + h * HDIM + c4);
                vv = *(const float4*)(V + tok * CDIM + h * HDIM + c4);
            }
            *(float4*)&Ks[r][c4] = kv;
            *(float4*)&Vs[r][c4] = vv;
        }
        am[tid] = g_attend[w * 512 + kc * 64 + tid];
        __syncthreads();

        for (int j = 0; j < 64; j++) {
            if (am[j]) {   // warp-uniform branch
                float s = 0.0f;
                const float4* kr = (const float4*)Ks[j];
#pragma unroll
                for (int dd = 0; dd < 16; dd++) {
                    float4 k4 = kr[dd];
                    s += q[4 * dd + 0] * k4.x + q[4 * dd + 1] * k4.y
                       + q[4 * dd + 2] * k4.z + q[4 * dd + 3] * k4.w;
                }
                s *= 0.125f;   // 1/sqrt(64)
                if (s > m) {
                    float corr = __expf(m - s);
                    l *= corr;
#pragma unroll
                    for (int d = 0; d < 64; d++) acc[d] *= corr;
                    m = s;
                }
                float pexp = __expf(s - m);
                l += pexp;
                const float4* vr = (const float4*)Vs[j];
#pragma unroll
                for (int dd = 0; dd < 16; dd++) {
                    float4 v4 = vr[dd];
                    acc[4 * dd + 0] += pexp * v4.x;
                    acc[4 * dd + 1] += pexp * v4.y;
                    acc[4 * dd + 2] += pexp * v4.z;
                    acc[4 * dd + 3] += pexp * v4.w;
                }
            }
        }
        __syncthreads();
    }
    float inv = 1.0f / l;
    float* op = AO + qtok * CDIM + h * HDIM;
#pragma unroll
    for (int i = 0; i < 16; i++) {
        float4 o4 = make_float4(acc[4 * i + 0] * inv, acc[4 * i + 1] * inv,
                                acc[4 * i + 2] * inv, acc[4 * i + 3] * inv);
        ((float4*)op)[i] = o4;
    }
}

// ---------------- launch ----------------------------------------------------
extern "C" void kernel_launch(void* const* d_in, const int* in_sizes, int n_in,
                              void* d_out, int out_size) {
    const float* x    = (const float*)d_in[0];
    const void*  pm   = d_in[1];
    const float* cosT = (const float*)d_in[2];
    const float* sinT = (const float*)d_in[3];
    const float* Wq   = (const float*)d_in[4];
    const float* bq   = (const float*)d_in[5];
    const float* Wk   = (const float*)d_in[6];
    const float* bk   = (const float*)d_in[7];
    const float* Wv   = (const float*)d_in[8];
    const float* bv   = (const float*)d_in[9];
    const float* Wo   = (const float*)d_in[10];
    const float* bo   = (const float*)d_in[11];
    float* out = (float*)d_out;

    float *Qp, *Kp, *Vp, *AOp;
    cudaGetSymbolAddress((void**)&Qp, g_Q);
    cudaGetSymbolAddress((void**)&Kp, g_K);
    cudaGetSymbolAddress((void**)&Vp, g_V);
    cudaGetSymbolAddress((void**)&AOp, g_AO);

    detect_mask<<<1, 256>>>((const unsigned int*)pm);
    build_attend<<<NWIN_TOT, 512>>>(pm);

    dim3 gg(CDIM / 128, NTOK / 128);   // (8, 128)
    sgemm_bias<<<gg, 256>>>(x, Wq, bq, Qp, NTOK, CDIM, CDIM);
    sgemm_bias<<<gg, 256>>>(x, Wk, bk, Kp, NTOK, CDIM, CDIM);
    sgemm_bias<<<gg, 256>>>(x, Wv, bv, Vp, NTOK, CDIM, CDIM);

    dim3 rg((NTOK * 512) / 256, 2);
    rope_kernel<<<rg, 256>>>(Qp, Kp, cosT, sinT);

    attn_kernel<<<NWIN_TOT * NHEAD * 4, 64>>>(Qp, Kp, Vp, AOp);

    sgemm_bias<<<gg, 256>>>(AOp, Wo, bo, out, NTOK, CDIM, CDIM);
}

// round 3
// speedup vs baseline: 2.1570x; 2.1570x over previous
#include <cuda_runtime.h>
#include <cuda_bf16.h>
#include <cstdint>

#define T_LEN 8192
#define BATCH 2
#define CDIM 1024
#define NHEAD 16
#define HDIM 64
#define WINSZ 256
#define NWIN_TOT 64
#define NTOK (BATCH * T_LEN)     // 16384
#define KP 3072                  // split-bf16 expanded K (3 x 1024)

// ---------------- scratch ----------------------------------------------------
__device__ float g_Q[(size_t)NTOK * CDIM];
__device__ float g_K[(size_t)NTOK * CDIM];
__device__ float g_V[(size_t)NTOK * CDIM];
__device__ float g_AO[(size_t)NTOK * CDIM];
__device__ __nv_bfloat16 g_A3[(size_t)NTOK * KP];        // x3, later AO3
__device__ __nv_bfloat16 g_B3[4][(size_t)CDIM * KP];     // Wq3,Wk3,Wv3,Wo3
__device__ unsigned char g_attend[NWIN_TOT * 512];
__device__ int g_maskmode;

// ---------------- helpers ------------------------------------------------------
__device__ __forceinline__ uint32_t smem_u32(const void* p) {
    uint32_t a;
    asm("{ .reg .u64 t; cvta.to.shared.u64 t, %1; cvt.u32.u64 %0, t; }" : "=r"(a) : "l"(p));
    return a;
}
__device__ __forceinline__ void cp16(uint32_t dst, const void* src) {
    asm volatile("cp.async.cg.shared.global [%0], [%1], 16;" :: "r"(dst), "l"(src));
}
__device__ __forceinline__ void cp_commit() { asm volatile("cp.async.commit_group;"); }
template <int N> __device__ __forceinline__ void cp_wait() {
    asm volatile("cp.async.wait_group %0;" :: "n"(N));
}
__device__ __forceinline__ void ldsm4(uint32_t (&r)[4], uint32_t addr) {
    asm volatile("ldmatrix.sync.aligned.m8n8.x4.shared.b16 {%0,%1,%2,%3}, [%4];"
                 : "=r"(r[0]), "=r"(r[1]), "=r"(r[2]), "=r"(r[3]) : "r"(addr));
}
__device__ __forceinline__ void mma16816(float (&c)[4], const uint32_t (&a)[4],
                                         uint32_t b0, uint32_t b1) {
    asm volatile(
        "mma.sync.aligned.m16n8k16.row.col.f32.bf16.bf16.f32 "
        "{%0,%1,%2,%3}, {%4,%5,%6,%7}, {%8,%9}, {%0,%1,%2,%3};"
        : "+f"(c[0]), "+f"(c[1]), "+f"(c[2]), "+f"(c[3])
        : "r"(a[0]), "r"(a[1]), "r"(a[2]), "r"(a[3]), "r"(b0), "r"(b1));
}

// ---------------- mma.sync split-bf16 GEMM -----------------------------------
// C[16384,1024] = A3[16384,3072] @ B3[1024,3072]^T + bias
// CTA tile 128x128, BK=64 (one SW128 atom row), 3-stage cp.async ring,
// 8 warps (4M x 2N), warp tile 32x64 via m16n8k16.
#define NST 3
#define CH 48                    // 3072 / 64
#define STAGE_B 32768            // A 16KB + B 16KB
#define SMEM_DYN (NST * STAGE_B)

__device__ __forceinline__ void load_chunk(uint32_t stage, const __nv_bfloat16* Arow,
                                           const __nv_bfloat16* Brow, int kbase, int tid) {
#pragma unroll
    for (int i = 0; i < 4; i++) {
        int f = tid + i * 256;            // 0..1023 : A tile segments
        int rr = f >> 3, seg = f & 7;
        uint32_t off = rr * 128 + seg * 16;
        uint32_t sw = off ^ ((off >> 3) & 0x70);
        cp16(stage + sw, Arow + (size_t)rr * KP + kbase + seg * 8);
        cp16(stage + 16384 + sw, Brow + (size_t)rr * KP + kbase + seg * 8);
    }
}

__global__ void __launch_bounds__(256) gemm_mma(const __nv_bfloat16* __restrict__ A,
        const __nv_bfloat16* __restrict__ Bw, const float* __restrict__ bias,
        float* __restrict__ C) {
    extern __shared__ char dsm[];
    uint32_t sbase = smem_u32(dsm);

    int tid = threadIdx.x;
    int wid = tid >> 5, lane = tid & 31;
    int row0 = blockIdx.y * 128;
    int col0 = blockIdx.x * 128;
    int m0 = (wid & 3) * 32;              // warp M offset in tile
    int n0 = (wid >> 2) * 64;             // warp N offset in tile

    const __nv_bfloat16* Arow = A + (size_t)row0 * KP;
    const __nv_bfloat16* Brow = Bw + (size_t)col0 * KP;

    // ldmatrix lane geometry
    int rA = m0 + (lane & 7) + ((lane >> 3) & 1) * 8;     // A row for this lane
    int ksegA = lane >> 4;                                 // 0/1 (16B halves of k16)
    int swA = rA & 7;
    int rB = n0 + (lane & 7) + ((lane >> 4) << 3);         // B n-row for this lane
    int ksegB = (lane >> 3) & 1;
    int swB = rB & 7;

    uint32_t aRowOff[2], bRowOff[4];
#pragma unroll
    for (int mi = 0; mi < 2; mi++) aRowOff[mi] = (uint32_t)(rA + mi * 16) * 128;
#pragma unroll
    for (int g = 0; g < 4; g++) bRowOff[g] = 16384u + (uint32_t)(rB + g * 16) * 128;

    float acc[2][8][4];
#pragma unroll
    for (int mi = 0; mi < 2; mi++)
#pragma unroll
        for (int nt = 0; nt < 8; nt++)
#pragma unroll
            for (int j = 0; j < 4; j++) acc[mi][nt][j] = 0.0f;

    // prologue: chunks 0,1
    load_chunk(sbase, Arow, Brow, 0, tid);
    cp_commit();
    load_chunk(sbase + STAGE_B, Arow, Brow, 64, tid);
    cp_commit();

    for (int c = 0; c < CH; c++) {
        if (c + 2 < CH) load_chunk(sbase + ((c + 2) % NST) * STAGE_B, Arow, Brow,
                                   (c + 2) * 64, tid);
        cp_commit();            // always commit (possibly empty) -> uniform wait depth
        cp_wait<2>();
        __syncthreads();

        uint32_t stg = sbase + (c % NST) * STAGE_B;
#pragma unroll
        for (int step = 0; step < 4; step++) {
            uint32_t a[2][4];
#pragma unroll
            for (int mi = 0; mi < 2; mi++)
                ldsm4(a[mi], stg + aRowOff[mi] + ((uint32_t)((step * 2 + ksegA) ^ swA) << 4));
            uint32_t b[4][4];
#pragma unroll
            for (int g = 0; g < 4; g++)
                ldsm4(b[g], stg + bRowOff[g] + ((uint32_t)((step * 2 + ksegB) ^ swB) << 4));
#pragma unroll
            for (int mi = 0; mi < 2; mi++)
#pragma unroll
                for (int nt = 0; nt < 8; nt++)
                    mma16816(acc[mi][nt], a[mi], b[nt >> 1][(nt & 1) * 2],
                             b[nt >> 1][(nt & 1) * 2 + 1]);
        }
        __syncthreads();
    }

    // epilogue: direct global store + bias
    int g = lane >> 2;
    int cl = (lane & 3) * 2;
#pragma unroll
    for (int mi = 0; mi < 2; mi++) {
#pragma unroll
        for (int nt = 0; nt < 8; nt++) {
            int gcol = col0 + n0 + nt * 8 + cl;
            float b0 = bias[gcol], b1 = bias[gcol + 1];
            int r0 = row0 + m0 + mi * 16 + g;
            float2 v0 = make_float2(acc[mi][nt][0] + b0, acc[mi][nt][1] + b1);
            float2 v1 = make_float2(acc[mi][nt][2] + b0, acc[mi][nt][3] + b1);
            *(float2*)(C + (size_t)r0 * CDIM + gcol) = v0;
            *(float2*)(C + (size_t)(r0 + 8) * CDIM + gcol) = v1;
        }
    }
}

// ---------------- fp32 -> split bf16 [hi,hi,lo] (A) or [hi,lo,hi] (B) -------
__global__ void split_kernel(const float* __restrict__ in, __nv_bfloat16* __restrict__ out,
                             int bmode) {
    int idx = blockIdx.x * blockDim.x + threadIdx.x;
    int m = idx >> 8;
    int k4 = (idx & 255) << 2;
    float4 v = *(const float4*)(in + (size_t)m * CDIM + k4);
    __nv_bfloat16 h[4], l[4];
    float vv[4] = {v.x, v.y, v.z, v.w};
#pragma unroll
    for (int i = 0; i < 4; i++) {
        h[i] = __float2bfloat16_rn(vv[i]);
        l[i] = __float2bfloat16_rn(vv[i] - __bfloat162float(h[i]));
    }
    size_t base = (size_t)m * KP + k4;
    __nv_bfloat162 h01; h01.x = h[0]; h01.y = h[1];
    __nv_bfloat162 h23; h23.x = h[2]; h23.y = h[3];
    __nv_bfloat162 l01; l01.x = l[0]; l01.y = l[1];
    __nv_bfloat162 l23; l23.x = l[2]; l23.y = l[3];
    *(__nv_bfloat162*)(out + base) = h01;
    *(__nv_bfloat162*)(out + base + 2) = h23;
    if (bmode) {  // B: hi, lo, hi
        *(__nv_bfloat162*)(out + base + 1024) = l01;
        *(__nv_bfloat162*)(out + base + 1026) = l23;
        *(__nv_bfloat162*)(out + base + 2048) = h01;
        *(__nv_bfloat162*)(out + base + 2050) = h23;
    } else {      // A: hi, hi, lo
        *(__nv_bfloat162*)(out + base + 1024) = h01;
        *(__nv_bfloat162*)(out + base + 1026) = h23;
        *(__nv_bfloat162*)(out + base + 2048) = l01;
        *(__nv_bfloat162*)(out + base + 2050) = l23;
    }
}

// ---------------- mask dtype detection + attend mask -------------------------
__global__ void detect_mask(const unsigned int* __restrict__ m) {
    __shared__ int okf, oki;
    if (threadIdx.x == 0) { okf = 1; oki = 1; }
    __syncthreads();
    for (int i = threadIdx.x; i < 4096; i += blockDim.x) {
        unsigned int w = m[i];
        if (w != 0u && w != 0x3f800000u) okf = 0;
        if (w > 1u) oki = 0;
    }
    __syncthreads();
    if (threadIdx.x == 0) g_maskmode = okf ? 2 : (oki ? 1 : 0);
}

__global__ void build_attend(const void* __restrict__ pm) {
    int w = blockIdx.x;
    int b = w >> 5;
    int wi = w & 31;
    int j = threadIdx.x;
    int p = wi * WINSZ - 128 + j;
    int attend = 1;
    if ((unsigned)p < (unsigned)T_LEN) {
        int mm = g_maskmode;
        size_t im = (size_t)b * T_LEN + p;
        int v;
        if (mm == 0)      v = ((const unsigned char*)pm)[im] != 0;
        else if (mm == 1) v = ((const int*)pm)[im] != 0;
        else              v = ((const float*)pm)[im] != 0.0f;
        attend = !v;
    }
    __shared__ int allb;
    if (j == 0) allb = 1;
    __syncthreads();
    if (!attend) allb = 0;
    __syncthreads();
    if (j == 0 && allb) attend = 0;
    g_attend[w * 512 + j] = (unsigned char)attend;
}

// ---------------- RoPE --------------------------------------------------------
__global__ void rope_kernel(float* __restrict__ Q, float* __restrict__ K,
                            const float* __restrict__ cosT,
                            const float* __restrict__ sinT) {
    int idx = blockIdx.x * blockDim.x + threadIdx.x;
    float* P = blockIdx.y ? K : Q;
    int token = idx >> 9;
    int r = idx & 511;
    int h = r >> 5;
    int d = r & 31;
    int pos = token & (T_LEN - 1);
    size_t base = (size_t)token * CDIM + h * HDIM;
    float a = P[base + d];
    float b = P[base + d + 32];
    float c1 = cosT[pos * HDIM + d], s1 = sinT[pos * HDIM + d];
    float c2 = cosT[pos * HDIM + d + 32], s2 = sinT[pos * HDIM + d + 32];
    P[base + d]      = a * c1 - b * s1;
    P[base + d + 32] = b * c2 + a * s2;
}

// ---------------- windowed attention (fp32 flash) -----------------------------
__global__ void __launch_bounds__(64) attn_kernel(
        const float* __restrict__ Q, const float* __restrict__ K,
        const float* __restrict__ V, float* __restrict__ AO) {
    __shared__ float Ks[64][64];
    __shared__ float Vs[64][64];
    __shared__ unsigned char am[64];

    int bid = blockIdx.x;
    int qc = bid & 3;
    int h = (bid >> 2) & 15;
    int w = bid >> 6;
    int b = w >> 5;
    int wi = w & 31;
    int tid = threadIdx.x;

    size_t qtok = (size_t)b * T_LEN + wi * WINSZ + qc * 64 + tid;
    const float* qp = Q + qtok * CDIM + h * HDIM;
    float q[64];
#pragma unroll
    for (int i = 0; i < 16; i++) {
        float4 t4 = ((const float4*)qp)[i];
        q[4 * i + 0] = t4.x; q[4 * i + 1] = t4.y;
        q[4 * i + 2] = t4.z; q[4 * i + 3] = t4.w;
    }
    float m = -1e30f, l = 0.0f;
    float acc[64];
#pragma unroll
    for (int d = 0; d < 64; d++) acc[d] = 0.0f;

    for (int kc = 0; kc < 8; kc++) {
        int base_p = wi * WINSZ - 128 + kc * 64;
#pragma unroll
        for (int it = 0; it < 16; it++) {
            int f = tid + it * 64;
            int r = f >> 4;
            int c4 = (f & 15) << 2;
            int p = base_p + r;
            float4 kv = make_float4(0.f, 0.f, 0.f, 0.f);
            float4 vv = make_float4(0.f, 0.f, 0.f, 0.f);
            if ((unsigned)p < (unsigned)T_LEN) {
                size_t tok = (size_t)b * T_LEN + p;
                kv = *(const float4*)(K + tok * CDIM + h * HDIM + c4);
                vv = *(const float4*)(V + tok * CDIM + h * HDIM + c4);
            }
            *(float4*)&Ks[r][c4] = kv;
            *(float4*)&Vs[r][c4] = vv;
        }
        am[tid] = g_attend[w * 512 + kc * 64 + tid];
        __syncthreads();

        for (int j = 0; j < 64; j++) {
            if (am[j]) {
                float s = 0.0f;
                const float4* kr = (const float4*)Ks[j];
#pragma unroll
                for (int dd = 0; dd < 16; dd++) {
                    float4 k4 = kr[dd];
                    s += q[4 * dd + 0] * k4.x + q[4 * dd + 1] * k4.y
                       + q[4 * dd + 2] * k4.z + q[4 * dd + 3] * k4.w;
                }
                s *= 0.125f;
                if (s > m) {
                    float corr = __expf(m - s);
                    l *= corr;
#pragma unroll
                    for (int d = 0; d < 64; d++) acc[d] *= corr;
                    m = s;
                }
                float pexp = __expf(s - m);
                l += pexp;
                const float4* vr = (const float4*)Vs[j];
#pragma unroll
                for (int dd = 0; dd < 16; dd++) {
                    float4 v4 = vr[dd];
                    acc[4 * dd + 0] += pexp * v4.x;
                    acc[4 * dd + 1] += pexp * v4.y;
                    acc[4 * dd + 2] += pexp * v4.z;
                    acc[4 * dd + 3] += pexp * v4.w;
                }
            }
        }
        __syncthreads();
    }
    float inv = 1.0f / l;
    float* op = AO + qtok * CDIM + h * HDIM;
#pragma unroll
    for (int i = 0; i < 16; i++) {
        float4 o4 = make_float4(acc[4 * i + 0] * inv, acc[4 * i + 1] * inv,
                                acc[4 * i + 2] * inv, acc[4 * i + 3] * inv);
        ((float4*)op)[i] = o4;
    }
}

// ---------------- launch --------------------------------------------------------
extern "C" void kernel_launch(void* const* d_in, const int* in_sizes, int n_in,
                              void* d_out, int out_size) {
    const float* x    = (const float*)d_in[0];
    const void*  pm   = d_in[1];
    const float* cosT = (const float*)d_in[2];
    const float* sinT = (const float*)d_in[3];
    const float* Wq   = (const float*)d_in[4];
    const float* bq   = (const float*)d_in[5];
    const float* Wk   = (const float*)d_in[6];
    const float* bk   = (const float*)d_in[7];
    const float* Wv   = (const float*)d_in[8];
    const float* bv   = (const float*)d_in[9];
    const float* Wo   = (const float*)d_in[10];
    const float* bo   = (const float*)d_in[11];
    float* out = (float*)d_out;

    float *Qp, *Kp, *Vp, *AOp;
    __nv_bfloat16 *A3, *B3;
    cudaGetSymbolAddress((void**)&Qp, g_Q);
    cudaGetSymbolAddress((void**)&Kp, g_K);
    cudaGetSymbolAddress((void**)&Vp, g_V);
    cudaGetSymbolAddress((void**)&AOp, g_AO);
    cudaGetSymbolAddress((void**)&A3, g_A3);
    cudaGetSymbolAddress((void**)&B3, g_B3);

    cudaFuncSetAttribute(gemm_mma, cudaFuncAttributeMaxDynamicSharedMemorySize, SMEM_DYN);

    detect_mask<<<1, 256>>>((const unsigned int*)pm);
    build_attend<<<NWIN_TOT, 512>>>(pm);

    split_kernel<<<NTOK, 256>>>(x, A3, 0);
    split_kernel<<<CDIM, 256>>>(Wq, B3 + 0 * (size_t)CDIM * KP, 1);
    split_kernel<<<CDIM, 256>>>(Wk, B3 + 1 * (size_t)CDIM * KP, 1);
    split_kernel<<<CDIM, 256>>>(Wv, B3 + 2 * (size_t)CDIM * KP, 1);
    split_kernel<<<CDIM, 256>>>(Wo, B3 + 3 * (size_t)CDIM * KP, 1);

    dim3 gg(CDIM / 128, NTOK / 128);   // x-major: A-tile L2 reuse across columns
    gemm_mma<<<gg, 256, SMEM_DYN>>>(A3, B3 + 0 * (size_t)CDIM * KP, bq, Qp);
    gemm_mma<<<gg, 256, SMEM_DYN>>>(A3, B3 + 1 * (size_t)CDIM * KP, bk, Kp);
    gemm_mma<<<gg, 256, SMEM_DYN>>>(A3, B3 + 2 * (size_t)CDIM * KP, bv, Vp);

    dim3 rg((NTOK * 512) / 256, 2);
    rope_kernel<<<rg, 256>>>(Qp, Kp, cosT, sinT);

    attn_kernel<<<NWIN_TOT * NHEAD * 4, 64>>>(Qp, Kp, Vp, AOp);

    split_kernel<<<NTOK, 256>>>(AOp, A3, 0);
    gemm_mma<<<gg, 256, SMEM_DYN>>>(A3, B3 + 3 * (size_t)CDIM * KP, bo, out);
}

// round 4
// speedup vs baseline: 2.8161x; 1.3056x over previous
#include <cuda_runtime.h>
#include <cuda_bf16.h>
#include <cstdint>

#define T_LEN 8192
#define BATCH 2
#define CDIM 1024
#define NHEAD 16
#define HDIM 64
#define WINSZ 256
#define NWIN_TOT 64
#define NTOK (BATCH * T_LEN)     // 16384
#define KP 3072                  // split-bf16 expanded K (3 x 1024)

// ---------------- scratch ----------------------------------------------------
__device__ float g_Q[(size_t)NTOK * CDIM];
__device__ float g_K[(size_t)NTOK * CDIM];
__device__ float g_V[(size_t)NTOK * CDIM];
__device__ float g_AO[(size_t)NTOK * CDIM];
__device__ __nv_bfloat16 g_A3[(size_t)NTOK * KP];
__device__ __nv_bfloat16 g_B3[4][(size_t)CDIM * KP];
__device__ __nv_bfloat16 g_QHL[(size_t)NTOK * NHEAD * 128];  // [tok*16+h][hi64|lo64]
__device__ __nv_bfloat16 g_KHL[(size_t)NTOK * NHEAD * 128];
__device__ __nv_bfloat16 g_VHL[(size_t)NTOK * NHEAD * 128];
__device__ unsigned char g_attend[NWIN_TOT * 512];
__device__ int g_maskmode;

// ---------------- helpers ------------------------------------------------------
__device__ __forceinline__ uint32_t smem_u32(const void* p) {
    uint32_t a;
    asm("{ .reg .u64 t; cvta.to.shared.u64 t, %1; cvt.u32.u64 %0, t; }" : "=r"(a) : "l"(p));
    return a;
}
__device__ __forceinline__ void cp16(uint32_t dst, const void* src) {
    asm volatile("cp.async.cg.shared.global [%0], [%1], 16;" :: "r"(dst), "l"(src));
}
__device__ __forceinline__ void cp16z(uint32_t dst, const void* src, uint32_t sz) {
    asm volatile("cp.async.cg.shared.global [%0], [%1], 16, %2;" :: "r"(dst), "l"(src), "r"(sz));
}
__device__ __forceinline__ void cp_commit() { asm volatile("cp.async.commit_group;"); }
template <int N> __device__ __forceinline__ void cp_wait() {
    asm volatile("cp.async.wait_group %0;" :: "n"(N));
}
__device__ __forceinline__ void ldsm4(uint32_t (&r)[4], uint32_t addr) {
    asm volatile("ldmatrix.sync.aligned.m8n8.x4.shared.b16 {%0,%1,%2,%3}, [%4];"
                 : "=r"(r[0]), "=r"(r[1]), "=r"(r[2]), "=r"(r[3]) : "r"(addr));
}
__device__ __forceinline__ void ldsm4t(uint32_t (&r)[4], uint32_t addr) {
    asm volatile("ldmatrix.sync.aligned.m8n8.x4.trans.shared.b16 {%0,%1,%2,%3}, [%4];"
                 : "=r"(r[0]), "=r"(r[1]), "=r"(r[2]), "=r"(r[3]) : "r"(addr));
}
__device__ __forceinline__ void mma16816(float (&c)[4], const uint32_t (&a)[4],
                                         uint32_t b0, uint32_t b1) {
    asm volatile(
        "mma.sync.aligned.m16n8k16.row.col.f32.bf16.bf16.f32 "
        "{%0,%1,%2,%3}, {%4,%5,%6,%7}, {%8,%9}, {%0,%1,%2,%3};"
        : "+f"(c[0]), "+f"(c[1]), "+f"(c[2]), "+f"(c[3])
        : "r"(a[0]), "r"(a[1]), "r"(a[2]), "r"(a[3]), "r"(b0), "r"(b1));
}
__device__ __forceinline__ uint32_t pack_bf16(float lo, float hi) {
    uint32_t r;
    asm("cvt.rn.bf16x2.f32 %0, %1, %2;" : "=r"(r) : "f"(hi), "f"(lo));
    return r;
}
__device__ __forceinline__ float bf_lo(uint32_t u) { return __uint_as_float(u << 16); }
__device__ __forceinline__ float bf_hi(uint32_t u) { return __uint_as_float(u & 0xffff0000u); }

// ---------------- mma.sync split-bf16 GEMM (unchanged from R3) ----------------
#define NST 3
#define CH 48
#define STAGE_B 32768
#define SMEM_DYN (NST * STAGE_B)

__device__ __forceinline__ void load_chunk(uint32_t stage, const __nv_bfloat16* Arow,
                                           const __nv_bfloat16* Brow, int kbase, int tid) {
#pragma unroll
    for (int i = 0; i < 4; i++) {
        int f = tid + i * 256;
        int rr = f >> 3, seg = f & 7;
        uint32_t off = rr * 128 + seg * 16;
        uint32_t sw = off ^ ((off >> 3) & 0x70);
        cp16(stage + sw, Arow + (size_t)rr * KP + kbase + seg * 8);
        cp16(stage + 16384 + sw, Brow + (size_t)rr * KP + kbase + seg * 8);
    }
}

__global__ void __launch_bounds__(256) gemm_mma(const __nv_bfloat16* __restrict__ A,
        const __nv_bfloat16* __restrict__ Bw, const float* __restrict__ bias,
        float* __restrict__ C) {
    extern __shared__ char dsm[];
    uint32_t sbase = smem_u32(dsm);

    int tid = threadIdx.x;
    int wid = tid >> 5, lane = tid & 31;
    int row0 = blockIdx.y * 128;
    int col0 = blockIdx.x * 128;
    int m0 = (wid & 3) * 32;
    int n0 = (wid >> 2) * 64;

    const __nv_bfloat16* Arow = A + (size_t)row0 * KP;
    const __nv_bfloat16* Brow = Bw + (size_t)col0 * KP;

    int rA = m0 + (lane & 7) + ((lane >> 3) & 1) * 8;
    int ksegA = lane >> 4;
    int swA = rA & 7;
    int rB = n0 + (lane & 7) + ((lane >> 4) << 3);
    int ksegB = (lane >> 3) & 1;
    int swB = rB & 7;

    uint32_t aRowOff[2], bRowOff[4];
#pragma unroll
    for (int mi = 0; mi < 2; mi++) aRowOff[mi] = (uint32_t)(rA + mi * 16) * 128;
#pragma unroll
    for (int g = 0; g < 4; g++) bRowOff[g] = 16384u + (uint32_t)(rB + g * 16) * 128;

    float acc[2][8][4];
#pragma unroll
    for (int mi = 0; mi < 2; mi++)
#pragma unroll
        for (int nt = 0; nt < 8; nt++)
#pragma unroll
            for (int j = 0; j < 4; j++) acc[mi][nt][j] = 0.0f;

    load_chunk(sbase, Arow, Brow, 0, tid);
    cp_commit();
    load_chunk(sbase + STAGE_B, Arow, Brow, 64, tid);
    cp_commit();

    for (int c = 0; c < CH; c++) {
        if (c + 2 < CH) load_chunk(sbase + ((c + 2) % NST) * STAGE_B, Arow, Brow,
                                   (c + 2) * 64, tid);
        cp_commit();
        cp_wait<2>();
        __syncthreads();

        uint32_t stg = sbase + (c % NST) * STAGE_B;
#pragma unroll
        for (int step = 0; step < 4; step++) {
            uint32_t a[2][4];
#pragma unroll
            for (int mi = 0; mi < 2; mi++)
                ldsm4(a[mi], stg + aRowOff[mi] + ((uint32_t)((step * 2 + ksegA) ^ swA) << 4));
            uint32_t b[4][4];
#pragma unroll
            for (int g = 0; g < 4; g++)
                ldsm4(b[g], stg + bRowOff[g] + ((uint32_t)((step * 2 + ksegB) ^ swB) << 4));
#pragma unroll
            for (int mi = 0; mi < 2; mi++)
#pragma unroll
                for (int nt = 0; nt < 8; nt++)
                    mma16816(acc[mi][nt], a[mi], b[nt >> 1][(nt & 1) * 2],
                             b[nt >> 1][(nt & 1) * 2 + 1]);
        }
        __syncthreads();
    }

    int g = lane >> 2;
    int cl = (lane & 3) * 2;
#pragma unroll
    for (int mi = 0; mi < 2; mi++) {
#pragma unroll
        for (int nt = 0; nt < 8; nt++) {
            int gcol = col0 + n0 + nt * 8 + cl;
            float b0 = bias[gcol], b1 = bias[gcol + 1];
            int r0 = row0 + m0 + mi * 16 + g;
            float2 v0 = make_float2(acc[mi][nt][0] + b0, acc[mi][nt][1] + b1);
            float2 v1 = make_float2(acc[mi][nt][2] + b0, acc[mi][nt][3] + b1);
            *(float2*)(C + (size_t)r0 * CDIM + gcol) = v0;
            *(float2*)(C + (size_t)(r0 + 8) * CDIM + gcol) = v1;
        }
    }
}

// ---------------- fp32 -> split bf16 (GEMM operands) -------------------------
__global__ void split_kernel(const float* __restrict__ in, __nv_bfloat16* __restrict__ out,
                             int bmode) {
    int idx = blockIdx.x * blockDim.x + threadIdx.x;
    int m = idx >> 8;
    int k4 = (idx & 255) << 2;
    float4 v = *(const float4*)(in + (size_t)m * CDIM + k4);
    __nv_bfloat16 h[4], l[4];
    float vv[4] = {v.x, v.y, v.z, v.w};
#pragma unroll
    for (int i = 0; i < 4; i++) {
        h[i] = __float2bfloat16_rn(vv[i]);
        l[i] = __float2bfloat16_rn(vv[i] - __bfloat162float(h[i]));
    }
    size_t base = (size_t)m * KP + k4;
    __nv_bfloat162 h01; h01.x = h[0]; h01.y = h[1];
    __nv_bfloat162 h23; h23.x = h[2]; h23.y = h[3];
    __nv_bfloat162 l01; l01.x = l[0]; l01.y = l[1];
    __nv_bfloat162 l23; l23.x = l[2]; l23.y = l[3];
    *(__nv_bfloat162*)(out + base) = h01;
    *(__nv_bfloat162*)(out + base + 2) = h23;
    if (bmode) {
        *(__nv_bfloat162*)(out + base + 1024) = l01;
        *(__nv_bfloat162*)(out + base + 1026) = l23;
        *(__nv_bfloat162*)(out + base + 2048) = h01;
        *(__nv_bfloat162*)(out + base + 2050) = h23;
    } else {
        *(__nv_bfloat162*)(out + base + 1024) = h01;
        *(__nv_bfloat162*)(out + base + 1026) = h23;
        *(__nv_bfloat162*)(out + base + 2048) = l01;
        *(__nv_bfloat162*)(out + base + 2050) = l23;
    }
}

// ---------------- mask dtype detection + attend mask -------------------------
__global__ void detect_mask(const unsigned int* __restrict__ m) {
    __shared__ int okf, oki;
    if (threadIdx.x == 0) { okf = 1; oki = 1; }
    __syncthreads();
    for (int i = threadIdx.x; i < 4096; i += blockDim.x) {
        unsigned int w = m[i];
        if (w != 0u && w != 0x3f800000u) okf = 0;
        if (w > 1u) oki = 0;
    }
    __syncthreads();
    if (threadIdx.x == 0) g_maskmode = okf ? 2 : (oki ? 1 : 0);
}

__global__ void build_attend(const void* __restrict__ pm) {
    int w = blockIdx.x;
    int b = w >> 5;
    int wi = w & 31;
    int j = threadIdx.x;
    int p = wi * WINSZ - 128 + j;
    int attend = 1;
    if ((unsigned)p < (unsigned)T_LEN) {
        int mm = g_maskmode;
        size_t im = (size_t)b * T_LEN + p;
        int v;
        if (mm == 0)      v = ((const unsigned char*)pm)[im] != 0;
        else if (mm == 1) v = ((const int*)pm)[im] != 0;
        else              v = ((const float*)pm)[im] != 0.0f;
        attend = !v;
    }
    __shared__ int allb;
    if (j == 0) allb = 1;
    __syncthreads();
    if (!attend) allb = 0;
    __syncthreads();
    if (j == 0 && allb) attend = 0;
    g_attend[w * 512 + j] = (unsigned char)attend;
}

// ---------------- fused rope + split (Q,K) / split (V) ------------------------
// out layout: [(token*16 + head)*128]: hi dims 0..63, lo dims 64..127
__global__ void rope_split(const float* __restrict__ Q, const float* __restrict__ K,
                           const float* __restrict__ V,
                           const float* __restrict__ cosT, const float* __restrict__ sinT,
                           __nv_bfloat16* __restrict__ QHL, __nv_bfloat16* __restrict__ KHL,
                           __nv_bfloat16* __restrict__ VHL) {
    int idx = blockIdx.x * blockDim.x + threadIdx.x;  // token*512 + h*32 + d
    int z = blockIdx.y;
    const float* src = (z == 0) ? Q : ((z == 1) ? K : V);
    __nv_bfloat16* dst = (z == 0) ? QHL : ((z == 1) ? KHL : VHL);
    int token = idx >> 9;
    int r = idx & 511;
    int hh = r >> 5;
    int d = r & 31;
    int pos = token & (T_LEN - 1);
    size_t base = (size_t)token * CDIM + hh * HDIM;
    float a = src[base + d];
    float bv = src[base + d + 32];
    float o1, o2;
    if (z < 2) {
        float c1 = cosT[pos * HDIM + d], s1 = sinT[pos * HDIM + d];
        float c2 = cosT[pos * HDIM + d + 32], s2 = sinT[pos * HDIM + d + 32];
        o1 = a * c1 - bv * s1;
        o2 = bv * c2 + a * s2;
    } else { o1 = a; o2 = bv; }
    size_t ob = ((size_t)token * NHEAD + hh) * 128;
    __nv_bfloat16 h1 = __float2bfloat16_rn(o1);
    __nv_bfloat16 h2 = __float2bfloat16_rn(o2);
    dst[ob + d] = h1;
    dst[ob + d + 32] = h2;
    dst[ob + 64 + d] = __float2bfloat16_rn(o1 - __bfloat162float(h1));
    dst[ob + 96 + d] = __float2bfloat16_rn(o2 - __bfloat162float(h2));
}

// ---------------- tensor-core windowed attention ------------------------------
// CTA = (head, window): 256 q rows, 8 warps x 32 rows. K chunks of 64, 2 stages.
// smem: QHI 32K | QLO 32K | stage0 32K (KHI,KLO,VHI,VLO 8K each) | stage1 32K | bias
#define ATT_Q_LO 32768
#define ATT_STG 65536
#define ATT_BIAS 131072
#define SMEM_ATTN (1024 + 131072 + 256)

__device__ __forceinline__ void load_kv_chunk(uint32_t stg, const __nv_bfloat16* KHL,
        const __nv_bfloat16* VHL, int b, int h, int p0, int tid) {
#pragma unroll
    for (int i = 0; i < 2; i++) {
        int f = tid + i * 256;              // 0..511 = 64 rows x 8 segs
        int r = f >> 3, seg = f & 7;
        int p = p0 + r;
        uint32_t ok = ((unsigned)p < (unsigned)T_LEN) ? 16u : 0u;
        int pc = (p < 0) ? 0 : ((p >= T_LEN) ? (T_LEN - 1) : p);
        const __nv_bfloat16* kk = KHL + (((size_t)(b * T_LEN + pc) * NHEAD + h) << 7) + seg * 8;
        const __nv_bfloat16* vv = VHL + (((size_t)(b * T_LEN + pc) * NHEAD + h) << 7) + seg * 8;
        uint32_t sw = (uint32_t)r * 128 + (uint32_t)(((seg ^ (r & 7)) << 4));
        cp16z(stg + sw, kk, ok);
        cp16z(stg + 8192 + sw, kk + 64, ok);
        cp16z(stg + 16384 + sw, vv, ok);
        cp16z(stg + 24576 + sw, vv + 64, ok);
    }
}

__global__ void __launch_bounds__(256) attn_mma(
        const __nv_bfloat16* __restrict__ QHL, const __nv_bfloat16* __restrict__ KHL,
        const __nv_bfloat16* __restrict__ VHL, float* __restrict__ AO) {
    extern __shared__ char sm[];
    char* smA = (char*)(((uintptr_t)sm + 1023) & ~(uintptr_t)1023);
    uint32_t sb = smem_u32(smA);
    float* biasP = (float*)(smA + ATT_BIAS);

    int h = blockIdx.x, w = blockIdx.y;
    int b = w >> 5, wi = w & 31;
    int tid = threadIdx.x, wid = tid >> 5, lane = tid & 31;
    int w0 = wid * 32;

    // lane geometry
    int rA = (lane & 7) + ((lane >> 3) & 1) * 8;   // A-frag row-in-16
    int ksegA = lane >> 4;
    int rB = (lane & 7) + ((lane >> 4) << 3);      // B-frag (K) row-in-16
    int ksegB = (lane >> 3) & 1;
    int krV = (lane & 7) + ((lane >> 4) << 3);     // V trans: key-row-in-16
    int nsegV = (lane >> 3) & 1;

    // ---- async loads: Q (whole 256 rows) + chunk0 -> group0; chunk1 -> group1
#pragma unroll
    for (int i = 0; i < 8; i++) {
        int f = tid + i * 256;                     // 0..2047 = 256 rows x 8 segs
        int r = f >> 3, seg = f & 7;
        const __nv_bfloat16* q = QHL + (((size_t)(b * T_LEN + wi * 256 + r) * NHEAD + h) << 7)
                                 + seg * 8;
        uint32_t sw = (uint32_t)r * 128 + (uint32_t)(((seg ^ (r & 7)) << 4));
        cp16(sb + sw, q);
        cp16(sb + ATT_Q_LO + sw, q + 64);
    }
    load_kv_chunk(sb + ATT_STG, KHL, VHL, b, h, wi * 256 - 128, tid);
    cp_commit();
    load_kv_chunk(sb + ATT_STG + 32768, KHL, VHL, b, h, wi * 256 - 64, tid);
    cp_commit();

    float O[2][8][4];
#pragma unroll
    for (int mi = 0; mi < 2; mi++)
#pragma unroll
        for (int nt = 0; nt < 8; nt++)
#pragma unroll
            for (int j = 0; j < 4; j++) O[mi][nt][j] = 0.0f;
    float mrow[4] = {-3e38f, -3e38f, -3e38f, -3e38f};
    float lrow[4] = {0.f, 0.f, 0.f, 0.f};

    for (int c = 0; c < 8; c++) {
        if (c < 6) { cp_wait<1>(); } else { cp_wait<0>(); }
        if (tid < 64)
            biasP[tid] = g_attend[w * 512 + c * 64 + tid] ? 0.0f : -1e30f;
        __syncthreads();

        uint32_t stg = sb + ATT_STG + (uint32_t)(c & 1) * 32768u;

        // ---- S = (Qhi Khi + Qhi Klo + Qlo Khi)
        float S[2][8][4];
#pragma unroll
        for (int mi = 0; mi < 2; mi++)
#pragma unroll
            for (int nt = 0; nt < 8; nt++)
#pragma unroll
                for (int j = 0; j < 4; j++) S[mi][nt][j] = 0.0f;

#pragma unroll
        for (int pass = 0; pass < 3; pass++) {
            uint32_t qoff = (pass == 2) ? (uint32_t)ATT_Q_LO : 0u;
            uint32_t koff = (pass == 1) ? 8192u : 0u;
#pragma unroll
            for (int step = 0; step < 4; step++) {
                uint32_t kb[4][4];
#pragma unroll
                for (int g = 0; g < 4; g++) {
                    int row = g * 16 + rB;
                    ldsm4(kb[g], stg + koff + (uint32_t)row * 128
                          + (uint32_t)(((step * 2 + ksegB) ^ (row & 7)) << 4));
                }
#pragma unroll
                for (int mi = 0; mi < 2; mi++) {
                    int rowQ = w0 + mi * 16 + rA;
                    uint32_t qf[4];
                    ldsm4(qf, sb + qoff + (uint32_t)rowQ * 128
                          + (uint32_t)(((step * 2 + ksegA) ^ (rowQ & 7)) << 4));
#pragma unroll
                    for (int nt = 0; nt < 8; nt++)
                        mma16816(S[mi][nt], qf, kb[nt >> 1][(nt & 1) * 2],
                                 kb[nt >> 1][(nt & 1) * 2 + 1]);
                }
            }
        }

        // ---- scale + bias + online softmax
        float2 bias[8];
#pragma unroll
        for (int nt = 0; nt < 8; nt++)
            bias[nt] = *(float2*)&biasP[nt * 8 + 2 * (lane & 3)];
#pragma unroll
        for (int mi = 0; mi < 2; mi++)
#pragma unroll
            for (int nt = 0; nt < 8; nt++) {
                S[mi][nt][0] = fmaf(S[mi][nt][0], 0.125f, bias[nt].x);
                S[mi][nt][1] = fmaf(S[mi][nt][1], 0.125f, bias[nt].y);
                S[mi][nt][2] = fmaf(S[mi][nt][2], 0.125f, bias[nt].x);
                S[mi][nt][3] = fmaf(S[mi][nt][3], 0.125f, bias[nt].y);
            }
#pragma unroll
        for (int mi = 0; mi < 2; mi++)
#pragma unroll
            for (int hh = 0; hh < 2; hh++) {
                int s = mi * 2 + hh;
                float rm = -3e38f;
#pragma unroll
                for (int nt = 0; nt < 8; nt++)
                    rm = fmaxf(rm, fmaxf(S[mi][nt][hh * 2], S[mi][nt][hh * 2 + 1]));
                rm = fmaxf(rm, __shfl_xor_sync(0xffffffffu, rm, 1));
                rm = fmaxf(rm, __shfl_xor_sync(0xffffffffu, rm, 2));
                float mn = fmaxf(mrow[s], rm);
                float sc = __expf(mrow[s] - mn);
                mrow[s] = mn;
                float ls = 0.0f;
#pragma unroll
                for (int nt = 0; nt < 8; nt++) {
                    float p0 = __expf(S[mi][nt][hh * 2] - mn);
                    float p1 = __expf(S[mi][nt][hh * 2 + 1] - mn);
                    S[mi][nt][hh * 2] = p0;
                    S[mi][nt][hh * 2 + 1] = p1;
                    ls += p0 + p1;
                    O[mi][nt][hh * 2] *= sc;
                    O[mi][nt][hh * 2 + 1] *= sc;
                }
                lrow[s] = lrow[s] * sc + ls;
            }

        // ---- O += (Phi Vhi + Plo Vhi + Phi Vlo)
#pragma unroll
        for (int step = 0; step < 4; step++) {
            uint32_t ah[2][4], al[2][4];
#pragma unroll
            for (int mi = 0; mi < 2; mi++)
#pragma unroll
                for (int t2 = 0; t2 < 2; t2++) {
                    float p0 = S[mi][2 * step + t2][0], p1 = S[mi][2 * step + t2][1];
                    float p2 = S[mi][2 * step + t2][2], p3 = S[mi][2 * step + t2][3];
                    uint32_t hA = pack_bf16(p0, p1);
                    uint32_t hB = pack_bf16(p2, p3);
                    ah[mi][t2 * 2] = hA;
                    ah[mi][t2 * 2 + 1] = hB;
                    al[mi][t2 * 2] = pack_bf16(p0 - bf_lo(hA), p1 - bf_hi(hA));
                    al[mi][t2 * 2 + 1] = pack_bf16(p2 - bf_lo(hB), p3 - bf_hi(hB));
                }
            uint32_t vb[4][4];
#pragma unroll
            for (int g = 0; g < 4; g++) {
                int vrow = step * 16 + krV;
                int seg = g * 2 + nsegV;
                ldsm4t(vb[g], stg + 16384u + (uint32_t)vrow * 128
                       + (uint32_t)(((seg ^ (vrow & 7)) << 4)));
            }
#pragma unroll
            for (int mi = 0; mi < 2; mi++)
#pragma unroll
                for (int nt = 0; nt < 8; nt++) {
                    uint32_t b0 = vb[nt >> 1][nt & 1], b1 = vb[nt >> 1][(nt & 1) + 2];
                    mma16816(O[mi][nt], ah[mi], b0, b1);
                    mma16816(O[mi][nt], al[mi], b0, b1);
                }
#pragma unroll
            for (int g = 0; g < 4; g++) {
                int vrow = step * 16 + krV;
                int seg = g * 2 + nsegV;
                ldsm4t(vb[g], stg + 24576u + (uint32_t)vrow * 128
                       + (uint32_t)(((seg ^ (vrow & 7)) << 4)));
            }
#pragma unroll
            for (int mi = 0; mi < 2; mi++)
#pragma unroll
                for (int nt = 0; nt < 8; nt++)
                    mma16816(O[mi][nt], ah[mi], vb[nt >> 1][nt & 1],
                             vb[nt >> 1][(nt & 1) + 2]);
        }

        __syncthreads();
        if (c + 2 < 8) {
            load_kv_chunk(sb + ATT_STG + (uint32_t)(c & 1) * 32768u, KHL, VHL, b, h,
                          wi * 256 - 128 + (c + 2) * 64, tid);
            cp_commit();
        }
    }

    // ---- normalize + store
#pragma unroll
    for (int s = 0; s < 4; s++) {
        lrow[s] += __shfl_xor_sync(0xffffffffu, lrow[s], 1);
        lrow[s] += __shfl_xor_sync(0xffffffffu, lrow[s], 2);
        lrow[s] = 1.0f / lrow[s];
    }
    int rr = lane >> 2, cc = 2 * (lane & 3);
#pragma unroll
    for (int mi = 0; mi < 2; mi++)
#pragma unroll
        for (int nt = 0; nt < 8; nt++) {
            int tok0 = b * T_LEN + wi * 256 + w0 + mi * 16 + rr;
            int col = h * 64 + nt * 8 + cc;
            float2 v0 = make_float2(O[mi][nt][0] * lrow[mi * 2],
                                    O[mi][nt][1] * lrow[mi * 2]);
            float2 v1 = make_float2(O[mi][nt][2] * lrow[mi * 2 + 1],
                                    O[mi][nt][3] * lrow[mi * 2 + 1]);
            *(float2*)(AO + (size_t)tok0 * CDIM + col) = v0;
            *(float2*)(AO + (size_t)(tok0 + 8) * CDIM + col) = v1;
        }
}

// ---------------- launch --------------------------------------------------------
extern "C" void kernel_launch(void* const* d_in, const int* in_sizes, int n_in,
                              void* d_out, int out_size) {
    const float* x    = (const float*)d_in[0];
    const void*  pm   = d_in[1];
    const float* cosT = (const float*)d_in[2];
    const float* sinT = (const float*)d_in[3];
    const float* Wq   = (const float*)d_in[4];
    const float* bq   = (const float*)d_in[5];
    const float* Wk   = (const float*)d_in[6];
    const float* bk   = (const float*)d_in[7];
    const float* Wv   = (const float*)d_in[8];
    const float* bv   = (const float*)d_in[9];
    const float* Wo   = (const float*)d_in[10];
    const float* bo   = (const float*)d_in[11];
    float* out = (float*)d_out;

    float *Qp, *Kp, *Vp, *AOp;
    __nv_bfloat16 *A3, *B3, *QHL, *KHL, *VHL;
    cudaGetSymbolAddress((void**)&Qp, g_Q);
    cudaGetSymbolAddress((void**)&Kp, g_K);
    cudaGetSymbolAddress((void**)&Vp, g_V);
    cudaGetSymbolAddress((void**)&AOp, g_AO);
    cudaGetSymbolAddress((void**)&A3, g_A3);
    cudaGetSymbolAddress((void**)&B3, g_B3);
    cudaGetSymbolAddress((void**)&QHL, g_QHL);
    cudaGetSymbolAddress((void**)&KHL, g_KHL);
    cudaGetSymbolAddress((void**)&VHL, g_VHL);

    cudaFuncSetAttribute(gemm_mma, cudaFuncAttributeMaxDynamicSharedMemorySize, SMEM_DYN);
    cudaFuncSetAttribute(attn_mma, cudaFuncAttributeMaxDynamicSharedMemorySize, SMEM_ATTN);

    detect_mask<<<1, 256>>>((const unsigned int*)pm);
    build_attend<<<NWIN_TOT, 512>>>(pm);

    split_kernel<<<NTOK, 256>>>(x, A3, 0);
    split_kernel<<<CDIM, 256>>>(Wq, B3 + 0 * (size_t)CDIM * KP, 1);
    split_kernel<<<CDIM, 256>>>(Wk, B3 + 1 * (size_t)CDIM * KP, 1);
    split_kernel<<<CDIM, 256>>>(Wv, B3 + 2 * (size_t)CDIM * KP, 1);
    split_kernel<<<CDIM, 256>>>(Wo, B3 + 3 * (size_t)CDIM * KP, 1);

    dim3 gg(CDIM / 128, NTOK / 128);
    gemm_mma<<<gg, 256, SMEM_DYN>>>(A3, B3 + 0 * (size_t)CDIM * KP, bq, Qp);
    gemm_mma<<<gg, 256, SMEM_DYN>>>(A3, B3 + 1 * (size_t)CDIM * KP, bk, Kp);
    gemm_mma<<<gg, 256, SMEM_DYN>>>(A3, B3 + 2 * (size_t)CDIM * KP, bv, Vp);

    dim3 rg((NTOK * 512) / 256, 3);
    rope_split<<<rg, 256>>>(Qp, Kp, Vp, cosT, sinT, QHL, KHL, VHL);

    attn_mma<<<dim3(NHEAD, NWIN_TOT), 256, SMEM_ATTN>>>(QHL, KHL, VHL, AOp);

    split_kernel<<<NTOK, 256>>>(AOp, A3, 0);
    gemm_mma<<<gg, 256, SMEM_DYN>>>(A3, B3 + 3 * (size_t)CDIM * KP, bo, out);
}

// round 5
// speedup vs baseline: 3.1482x; 1.1179x over previous
#include <cuda_runtime.h>
#include <cuda_bf16.h>
#include <cstdint>

#define T_LEN 8192
#define BATCH 2
#define CDIM 1024
#define NHEAD 16
#define HDIM 64
#define WINSZ 256
#define NWIN_TOT 64
#define NTOK (BATCH * T_LEN)     // 16384

// ---------------- scratch ----------------------------------------------------
__device__ float g_Q[(size_t)NTOK * CDIM];
__device__ float g_K[(size_t)NTOK * CDIM];
__device__ float g_V[(size_t)NTOK * CDIM];
__device__ float g_AO[(size_t)NTOK * CDIM];
__device__ __nv_bfloat16 g_QHL[(size_t)NTOK * NHEAD * 128];  // [tok*16+h][hi64|lo64]
__device__ __nv_bfloat16 g_KHL[(size_t)NTOK * NHEAD * 128];
__device__ __nv_bfloat16 g_VHL[(size_t)NTOK * NHEAD * 128];
__device__ unsigned char g_attend[NWIN_TOT * 512];
__device__ int g_maskmode;

// ---------------- helpers ------------------------------------------------------
__device__ __forceinline__ uint32_t smem_u32(const void* p) {
    uint32_t a;
    asm("{ .reg .u64 t; cvta.to.shared.u64 t, %1; cvt.u32.u64 %0, t; }" : "=r"(a) : "l"(p));
    return a;
}
__device__ __forceinline__ void cp16(uint32_t dst, const void* src) {
    asm volatile("cp.async.cg.shared.global [%0], [%1], 16;" :: "r"(dst), "l"(src));
}
__device__ __forceinline__ void cp16z(uint32_t dst, const void* src, uint32_t sz) {
    asm volatile("cp.async.cg.shared.global [%0], [%1], 16, %2;" :: "r"(dst), "l"(src), "r"(sz));
}
__device__ __forceinline__ void cp_commit() { asm volatile("cp.async.commit_group;"); }
template <int N> __device__ __forceinline__ void cp_wait() {
    asm volatile("cp.async.wait_group %0;" :: "n"(N));
}
__device__ __forceinline__ void ldsm4(uint32_t (&r)[4], uint32_t addr) {
    asm volatile("ldmatrix.sync.aligned.m8n8.x4.shared.b16 {%0,%1,%2,%3}, [%4];"
                 : "=r"(r[0]), "=r"(r[1]), "=r"(r[2]), "=r"(r[3]) : "r"(addr));
}
__device__ __forceinline__ void ldsm4t(uint32_t (&r)[4], uint32_t addr) {
    asm volatile("ldmatrix.sync.aligned.m8n8.x4.trans.shared.b16 {%0,%1,%2,%3}, [%4];"
                 : "=r"(r[0]), "=r"(r[1]), "=r"(r[2]), "=r"(r[3]) : "r"(addr));
}
__device__ __forceinline__ void mma16816(float (&c)[4], const uint32_t (&a)[4],
                                         uint32_t b0, uint32_t b1) {
    asm volatile(
        "mma.sync.aligned.m16n8k16.row.col.f32.bf16.bf16.f32 "
        "{%0,%1,%2,%3}, {%4,%5,%6,%7}, {%8,%9}, {%0,%1,%2,%3};"
        : "+f"(c[0]), "+f"(c[1]), "+f"(c[2]), "+f"(c[3])
        : "r"(a[0]), "r"(a[1]), "r"(a[2]), "r"(a[3]), "r"(b0), "r"(b1));
}
__device__ __forceinline__ void mma_tf32(float (&c)[4], const uint32_t (&a)[4],
                                         uint32_t b0, uint32_t b1) {
    asm volatile(
        "mma.sync.aligned.m16n8k8.row.col.f32.tf32.tf32.f32 "
        "{%0,%1,%2,%3}, {%4,%5,%6,%7}, {%8,%9}, {%0,%1,%2,%3};"
        : "+f"(c[0]), "+f"(c[1]), "+f"(c[2]), "+f"(c[3])
        : "r"(a[0]), "r"(a[1]), "r"(a[2]), "r"(a[3]), "r"(b0), "r"(b1));
}
__device__ __forceinline__ uint32_t pack_bf16(float lo, float hi) {
    uint32_t r;
    asm("cvt.rn.bf16x2.f32 %0, %1, %2;" : "=r"(r) : "f"(hi), "f"(lo));
    return r;
}
__device__ __forceinline__ float bf_lo(uint32_t u) { return __uint_as_float(u << 16); }
__device__ __forceinline__ float bf_hi(uint32_t u) { return __uint_as_float(u & 0xffff0000u); }
__device__ __forceinline__ uint32_t ld_tf32(const char* smA, uint32_t off) {
    float f = *(const float*)(smA + off);
    uint32_t r;
    asm("cvt.rna.tf32.f32 %0, %1;" : "=r"(r) : "f"(f));
    return r;
}

// ---------------- TF32 GEMM: C[M,1024] = A[M,1024] @ W[1024,1024]^T + bias ----
// CTA 128x128, BK=32, 3-stage cp.async ring, 8 warps (4M x 2N), warp tile 32x64.
// smem rows stride 36 floats (144B): lane->bank map (4g+c) is a permutation.
#define GK 1024
#define GCH 32                    // 1024 / 32
#define GSTG 36864                // (128 A rows + 128 B rows) * 144B
#define GB_OFF 18432
#define SMEM_GEMM (3 * GSTG)

__device__ __forceinline__ void g_load_chunk(uint32_t stage, const float* Arow,
                                             const float* Brow, int kbase, int tid) {
#pragma unroll
    for (int i = 0; i < 4; i++) {
        int f = tid + i * 256;            // 0..1023 = 128 rows x 8 segs(16B)
        int rr = f >> 3, seg = f & 7;
        uint32_t dst = stage + (uint32_t)rr * 144 + (uint32_t)seg * 16;
        cp16(dst, Arow + (size_t)rr * GK + kbase + seg * 4);
        cp16(dst + GB_OFF, Brow + (size_t)rr * GK + kbase + seg * 4);
    }
}

__global__ void __launch_bounds__(256) gemm_tf32(const float* __restrict__ A,
        const float* __restrict__ W, const float* __restrict__ bias,
        float* __restrict__ C) {
    extern __shared__ char dsm[];
    int tid = threadIdx.x;
    int wid = tid >> 5, lane = tid & 31;
    int row0 = blockIdx.y * 128;
    int col0 = blockIdx.x * 128;
    int m0 = (wid & 3) * 32;
    int n0 = (wid >> 2) * 64;
    int gp = lane >> 2;              // group 0..7
    int ci = lane & 3;               // thread-in-group 0..3

    const float* Arow = A + (size_t)row0 * GK;
    const float* Brow = W + (size_t)col0 * GK;

    // byte offsets inside a stage
    uint32_t aBase[2], bBase[8];
#pragma unroll
    for (int mi = 0; mi < 2; mi++)
        aBase[mi] = (uint32_t)(m0 + mi * 16 + gp) * 144 + (uint32_t)ci * 4;
#pragma unroll
    for (int nt = 0; nt < 8; nt++)
        bBase[nt] = (uint32_t)GB_OFF + (uint32_t)(n0 + nt * 8 + gp) * 144 + (uint32_t)ci * 4;

    float acc[2][8][4];
#pragma unroll
    for (int mi = 0; mi < 2; mi++)
#pragma unroll
        for (int nt = 0; nt < 8; nt++)
#pragma unroll
            for (int j = 0; j < 4; j++) acc[mi][nt][j] = 0.0f;

    uint32_t sb = smem_u32(dsm);
    g_load_chunk(sb, Arow, Brow, 0, tid);
    cp_commit();
    g_load_chunk(sb + GSTG, Arow, Brow, 32, tid);
    cp_commit();

    for (int c = 0; c < GCH; c++) {
        if (c + 2 < GCH)
            g_load_chunk(sb + (uint32_t)((c + 2) % 3) * GSTG, Arow, Brow, (c + 2) * 32, tid);
        cp_commit();
        cp_wait<2>();
        __syncthreads();

        const char* stg = dsm + (size_t)(c % 3) * GSTG;
#pragma unroll
        for (int ks = 0; ks < 4; ks++) {
            uint32_t koff = (uint32_t)ks * 32;       // 8 floats per k-step
            uint32_t b[8][2];
#pragma unroll
            for (int nt = 0; nt < 8; nt++) {
                b[nt][0] = ld_tf32(stg, bBase[nt] + koff);
                b[nt][1] = ld_tf32(stg, bBase[nt] + koff + 16);
            }
#pragma unroll
            for (int mi = 0; mi < 2; mi++) {
                uint32_t a[4];
                a[0] = ld_tf32(stg, aBase[mi] + koff);
                a[1] = ld_tf32(stg, aBase[mi] + 1152 + koff);        // +8 rows
                a[2] = ld_tf32(stg, aBase[mi] + koff + 16);          // +4 cols
                a[3] = ld_tf32(stg, aBase[mi] + 1152 + koff + 16);
#pragma unroll
                for (int nt = 0; nt < 8; nt++)
                    mma_tf32(acc[mi][nt], a, b[nt][0], b[nt][1]);
            }
        }
        __syncthreads();
    }

    int cl = ci * 2;
#pragma unroll
    for (int mi = 0; mi < 2; mi++) {
#pragma unroll
        for (int nt = 0; nt < 8; nt++) {
            int gcol = col0 + n0 + nt * 8 + cl;
            float b0 = bias[gcol], b1 = bias[gcol + 1];
            int r0 = row0 + m0 + mi * 16 + gp;
            float2 v0 = make_float2(acc[mi][nt][0] + b0, acc[mi][nt][1] + b1);
            float2 v1 = make_float2(acc[mi][nt][2] + b0, acc[mi][nt][3] + b1);
            *(float2*)(C + (size_t)r0 * CDIM + gcol) = v0;
            *(float2*)(C + (size_t)(r0 + 8) * CDIM + gcol) = v1;
        }
    }
}

// ---------------- mask dtype detection + attend mask -------------------------
__global__ void detect_mask(const unsigned int* __restrict__ m) {
    __shared__ int okf, oki;
    if (threadIdx.x == 0) { okf = 1; oki = 1; }
    __syncthreads();
    for (int i = threadIdx.x; i < 4096; i += blockDim.x) {
        unsigned int w = m[i];
        if (w != 0u && w != 0x3f800000u) okf = 0;
        if (w > 1u) oki = 0;
    }
    __syncthreads();
    if (threadIdx.x == 0) g_maskmode = okf ? 2 : (oki ? 1 : 0);
}

__global__ void build_attend(const void* __restrict__ pm) {
    int w = blockIdx.x;
    int b = w >> 5;
    int wi = w & 31;
    int j = threadIdx.x;
    int p = wi * WINSZ - 128 + j;
    int attend = 1;
    if ((unsigned)p < (unsigned)T_LEN) {
        int mm = g_maskmode;
        size_t im = (size_t)b * T_LEN + p;
        int v;
        if (mm == 0)      v = ((const unsigned char*)pm)[im] != 0;
        else if (mm == 1) v = ((const int*)pm)[im] != 0;
        else              v = ((const float*)pm)[im] != 0.0f;
        attend = !v;
    }
    __shared__ int allb;
    if (j == 0) allb = 1;
    __syncthreads();
    if (!attend) allb = 0;
    __syncthreads();
    if (j == 0 && allb) attend = 0;
    g_attend[w * 512 + j] = (unsigned char)attend;
}

// ---------------- fused rope + split (Q,K) / split (V) ------------------------
__global__ void rope_split(const float* __restrict__ Q, const float* __restrict__ K,
                           const float* __restrict__ V,
                           const float* __restrict__ cosT, const float* __restrict__ sinT,
                           __nv_bfloat16* __restrict__ QHL, __nv_bfloat16* __restrict__ KHL,
                           __nv_bfloat16* __restrict__ VHL) {
    int idx = blockIdx.x * blockDim.x + threadIdx.x;
    int z = blockIdx.y;
    const float* src = (z == 0) ? Q : ((z == 1) ? K : V);
    __nv_bfloat16* dst = (z == 0) ? QHL : ((z == 1) ? KHL : VHL);
    int token = idx >> 9;
    int r = idx & 511;
    int hh = r >> 5;
    int d = r & 31;
    int pos = token & (T_LEN - 1);
    size_t base = (size_t)token * CDIM + hh * HDIM;
    float a = src[base + d];
    float bv = src[base + d + 32];
    float o1, o2;
    if (z < 2) {
        float c1 = cosT[pos * HDIM + d], s1 = sinT[pos * HDIM + d];
        float c2 = cosT[pos * HDIM + d + 32], s2 = sinT[pos * HDIM + d + 32];
        o1 = a * c1 - bv * s1;
        o2 = bv * c2 + a * s2;
    } else { o1 = a; o2 = bv; }
    size_t ob = ((size_t)token * NHEAD + hh) * 128;
    __nv_bfloat16 h1 = __float2bfloat16_rn(o1);
    __nv_bfloat16 h2 = __float2bfloat16_rn(o2);
    dst[ob + d] = h1;
    dst[ob + d + 32] = h2;
    dst[ob + 64 + d] = __float2bfloat16_rn(o1 - __bfloat162float(h1));
    dst[ob + 96 + d] = __float2bfloat16_rn(o2 - __bfloat162float(h2));
}

// ---------------- tensor-core windowed attention (unchanged from R4) ---------
#define ATT_Q_LO 32768
#define ATT_STG 65536
#define ATT_BIAS 131072
#define SMEM_ATTN (1024 + 131072 + 256)

__device__ __forceinline__ void load_kv_chunk(uint32_t stg, const __nv_bfloat16* KHL,
        const __nv_bfloat16* VHL, int b, int h, int p0, int tid) {
#pragma unroll
    for (int i = 0; i < 2; i++) {
        int f = tid + i * 256;
        int r = f >> 3, seg = f & 7;
        int p = p0 + r;
        uint32_t ok = ((unsigned)p < (unsigned)T_LEN) ? 16u : 0u;
        int pc = (p < 0) ? 0 : ((p >= T_LEN) ? (T_LEN - 1) : p);
        const __nv_bfloat16* kk = KHL + (((size_t)(b * T_LEN + pc) * NHEAD + h) << 7) + seg * 8;
        const __nv_bfloat16* vv = VHL + (((size_t)(b * T_LEN + pc) * NHEAD + h) << 7) + seg * 8;
        uint32_t sw = (uint32_t)r * 128 + (uint32_t)(((seg ^ (r & 7)) << 4));
        cp16z(stg + sw, kk, ok);
        cp16z(stg + 8192 + sw, kk + 64, ok);
        cp16z(stg + 16384 + sw, vv, ok);
        cp16z(stg + 24576 + sw, vv + 64, ok);
    }
}

__global__ void __launch_bounds__(256) attn_mma(
        const __nv_bfloat16* __restrict__ QHL, const __nv_bfloat16* __restrict__ KHL,
        const __nv_bfloat16* __restrict__ VHL, float* __restrict__ AO) {
    extern __shared__ char sm[];
    char* smA = (char*)(((uintptr_t)sm + 1023) & ~(uintptr_t)1023);
    uint32_t sb = smem_u32(smA);
    float* biasP = (float*)(smA + ATT_BIAS);

    int h = blockIdx.x, w = blockIdx.y;
    int b = w >> 5, wi = w & 31;
    int tid = threadIdx.x, wid = tid >> 5, lane = tid & 31;
    int w0 = wid * 32;

    int rA = (lane & 7) + ((lane >> 3) & 1) * 8;
    int ksegA = lane >> 4;
    int rB = (lane & 7) + ((lane >> 4) << 3);
    int ksegB = (lane >> 3) & 1;
    int krV = (lane & 7) + ((lane >> 4) << 3);
    int nsegV = (lane >> 3) & 1;

#pragma unroll
    for (int i = 0; i < 8; i++) {
        int f = tid + i * 256;
        int r = f >> 3, seg = f & 7;
        const __nv_bfloat16* q = QHL + (((size_t)(b * T_LEN + wi * 256 + r) * NHEAD + h) << 7)
                                 + seg * 8;
        uint32_t sw = (uint32_t)r * 128 + (uint32_t)(((seg ^ (r & 7)) << 4));
        cp16(sb + sw, q);
        cp16(sb + ATT_Q_LO + sw, q + 64);
    }
    load_kv_chunk(sb + ATT_STG, KHL, VHL, b, h, wi * 256 - 128, tid);
    cp_commit();
    load_kv_chunk(sb + ATT_STG + 32768, KHL, VHL, b, h, wi * 256 - 64, tid);
    cp_commit();

    float O[2][8][4];
#pragma unroll
    for (int mi = 0; mi < 2; mi++)
#pragma unroll
        for (int nt = 0; nt < 8; nt++)
#pragma unroll
            for (int j = 0; j < 4; j++) O[mi][nt][j] = 0.0f;
    float mrow[4] = {-3e38f, -3e38f, -3e38f, -3e38f};
    float lrow[4] = {0.f, 0.f, 0.f, 0.f};

    for (int c = 0; c < 8; c++) {
        if (c < 6) { cp_wait<1>(); } else { cp_wait<0>(); }
        if (tid < 64)
            biasP[tid] = g_attend[w * 512 + c * 64 + tid] ? 0.0f : -1e30f;
        __syncthreads();

        uint32_t stg = sb + ATT_STG + (uint32_t)(c & 1) * 32768u;

        float S[2][8][4];
#pragma unroll
        for (int mi = 0; mi < 2; mi++)
#pragma unroll
            for (int nt = 0; nt < 8; nt++)
#pragma unroll
                for (int j = 0; j < 4; j++) S[mi][nt][j] = 0.0f;

#pragma unroll
        for (int pass = 0; pass < 3; pass++) {
            uint32_t qoff = (pass == 2) ? (uint32_t)ATT_Q_LO : 0u;
            uint32_t koff = (pass == 1) ? 8192u : 0u;
#pragma unroll
            for (int step = 0; step < 4; step++) {
                uint32_t kb[4][4];
#pragma unroll
                for (int g = 0; g < 4; g++) {
                    int row = g * 16 + rB;
                    ldsm4(kb[g], stg + koff + (uint32_t)row * 128
                          + (uint32_t)(((step * 2 + ksegB) ^ (row & 7)) << 4));
                }
#pragma unroll
                for (int mi = 0; mi < 2; mi++) {
                    int rowQ = w0 + mi * 16 + rA;
                    uint32_t qf[4];
                    ldsm4(qf, sb + qoff + (uint32_t)rowQ * 128
                          + (uint32_t)(((step * 2 + ksegA) ^ (rowQ & 7)) << 4));
#pragma unroll
                    for (int nt = 0; nt < 8; nt++)
                        mma16816(S[mi][nt], qf, kb[nt >> 1][(nt & 1) * 2],
                                 kb[nt >> 1][(nt & 1) * 2 + 1]);
                }
            }
        }

        float2 bias[8];
#pragma unroll
        for (int nt = 0; nt < 8; nt++)
            bias[nt] = *(float2*)&biasP[nt * 8 + 2 * (lane & 3)];
#pragma unroll
        for (int mi = 0; mi < 2; mi++)
#pragma unroll
            for (int nt = 0; nt < 8; nt++) {
                S[mi][nt][0] = fmaf(S[mi][nt][0], 0.125f, bias[nt].x);
                S[mi][nt][1] = fmaf(S[mi][nt][1], 0.125f, bias[nt].y);
                S[mi][nt][2] = fmaf(S[mi][nt][2], 0.125f, bias[nt].x);
                S[mi][nt][3] = fmaf(S[mi][nt][3], 0.125f, bias[nt].y);
            }
#pragma unroll
        for (int mi = 0; mi < 2; mi++)
#pragma unroll
            for (int hh = 0; hh < 2; hh++) {
                int s = mi * 2 + hh;
                float rm = -3e38f;
#pragma unroll
                for (int nt = 0; nt < 8; nt++)
                    rm = fmaxf(rm, fmaxf(S[mi][nt][hh * 2], S[mi][nt][hh * 2 + 1]));
                rm = fmaxf(rm, __shfl_xor_sync(0xffffffffu, rm, 1));
                rm = fmaxf(rm, __shfl_xor_sync(0xffffffffu, rm, 2));
                float mn = fmaxf(mrow[s], rm);
                float sc = __expf(mrow[s] - mn);
                mrow[s] = mn;
                float ls = 0.0f;
#pragma unroll
                for (int nt = 0; nt < 8; nt++) {
                    float p0 = __expf(S[mi][nt][hh * 2] - mn);
                    float p1 = __expf(S[mi][nt][hh * 2 + 1] - mn);
                    S[mi][nt][hh * 2] = p0;
                    S[mi][nt][hh * 2 + 1] = p1;
                    ls += p0 + p1;
                    O[mi][nt][hh * 2] *= sc;
                    O[mi][nt][hh * 2 + 1] *= sc;
                }
                lrow[s] = lrow[s] * sc + ls;
            }

#pragma unroll
        for (int step = 0; step < 4; step++) {
            uint32_t ah[2][4], al[2][4];
#pragma unroll
            for (int mi = 0; mi < 2; mi++)
#pragma unroll
                for (int t2 = 0; t2 < 2; t2++) {
                    float p0 = S[mi][2 * step + t2][0], p1 = S[mi][2 * step + t2][1];
                    float p2 = S[mi][2 * step + t2][2], p3 = S[mi][2 * step + t2][3];
                    uint32_t hA = pack_bf16(p0, p1);
                    uint32_t hB = pack_bf16(p2, p3);
                    ah[mi][t2 * 2] = hA;
                    ah[mi][t2 * 2 + 1] = hB;
                    al[mi][t2 * 2] = pack_bf16(p0 - bf_lo(hA), p1 - bf_hi(hA));
                    al[mi][t2 * 2 + 1] = pack_bf16(p2 - bf_lo(hB), p3 - bf_hi(hB));
                }
            uint32_t vb[4][4];
#pragma unroll
            for (int g = 0; g < 4; g++) {
                int vrow = step * 16 + krV;
                int seg = g * 2 + nsegV;
                ldsm4t(vb[g], stg + 16384u + (uint32_t)vrow * 128
                       + (uint32_t)(((seg ^ (vrow & 7)) << 4)));
            }
#pragma unroll
            for (int mi = 0; mi < 2; mi++)
#pragma unroll
                for (int nt = 0; nt < 8; nt++) {
                    uint32_t b0 = vb[nt >> 1][nt & 1], b1 = vb[nt >> 1][(nt & 1) + 2];
                    mma16816(O[mi][nt], ah[mi], b0, b1);
                    mma16816(O[mi][nt], al[mi], b0, b1);
                }
#pragma unroll
            for (int g = 0; g < 4; g++) {
                int vrow = step * 16 + krV;
                int seg = g * 2 + nsegV;
                ldsm4t(vb[g], stg + 24576u + (uint32_t)vrow * 128
                       + (uint32_t)(((seg ^ (vrow & 7)) << 4)));
            }
#pragma unroll
            for (int mi = 0; mi < 2; mi++)
#pragma unroll
                for (int nt = 0; nt < 8; nt++)
                    mma16816(O[mi][nt], ah[mi], vb[nt >> 1][nt & 1],
                             vb[nt >> 1][(nt & 1) + 2]);
        }

        __syncthreads();
        if (c + 2 < 8) {
            load_kv_chunk(sb + ATT_STG + (uint32_t)(c & 1) * 32768u, KHL, VHL, b, h,
                          wi * 256 - 128 + (c + 2) * 64, tid);
            cp_commit();
        }
    }

#pragma unroll
    for (int s = 0; s < 4; s++) {
        lrow[s] += __shfl_xor_sync(0xffffffffu, lrow[s], 1);
        lrow[s] += __shfl_xor_sync(0xffffffffu, lrow[s], 2);
        lrow[s] = 1.0f / lrow[s];
    }
    int rr = lane >> 2, cc = 2 * (lane & 3);
#pragma unroll
    for (int mi = 0; mi < 2; mi++)
#pragma unroll
        for (int nt = 0; nt < 8; nt++) {
            int tok0 = b * T_LEN + wi * 256 + w0 + mi * 16 + rr;
            int col = h * 64 + nt * 8 + cc;
            float2 v0 = make_float2(O[mi][nt][0] * lrow[mi * 2],
                                    O[mi][nt][1] * lrow[mi * 2]);
            float2 v1 = make_float2(O[mi][nt][2] * lrow[mi * 2 + 1],
                                    O[mi][nt][3] * lrow[mi * 2 + 1]);
            *(float2*)(AO + (size_t)tok0 * CDIM + col) = v0;
            *(float2*)(AO + (size_t)(tok0 + 8) * CDIM + col) = v1;
        }
}

// ---------------- launch --------------------------------------------------------
extern "C" void kernel_launch(void* const* d_in, const int* in_sizes, int n_in,
                              void* d_out, int out_size) {
    const float* x    = (const float*)d_in[0];
    const void*  pm   = d_in[1];
    const float* cosT = (const float*)d_in[2];
    const float* sinT = (const float*)d_in[3];
    const float* Wq   = (const float*)d_in[4];
    const float* bq   = (const float*)d_in[5];
    const float* Wk   = (const float*)d_in[6];
    const float* bk   = (const float*)d_in[7];
    const float* Wv   = (const float*)d_in[8];
    const float* bv   = (const float*)d_in[9];
    const float* Wo   = (const float*)d_in[10];
    const float* bo   = (const float*)d_in[11];
    float* out = (float*)d_out;

    float *Qp, *Kp, *Vp, *AOp;
    __nv_bfloat16 *QHL, *KHL, *VHL;
    cudaGetSymbolAddress((void**)&Qp, g_Q);
    cudaGetSymbolAddress((void**)&Kp, g_K);
    cudaGetSymbolAddress((void**)&Vp, g_V);
    cudaGetSymbolAddress((void**)&AOp, g_AO);
    cudaGetSymbolAddress((void**)&QHL, g_QHL);
    cudaGetSymbolAddress((void**)&KHL, g_KHL);
    cudaGetSymbolAddress((void**)&VHL, g_VHL);

    cudaFuncSetAttribute(gemm_tf32, cudaFuncAttributeMaxDynamicSharedMemorySize, SMEM_GEMM);
    cudaFuncSetAttribute(attn_mma, cudaFuncAttributeMaxDynamicSharedMemorySize, SMEM_ATTN);

    detect_mask<<<1, 256>>>((const unsigned int*)pm);
    build_attend<<<NWIN_TOT, 512>>>(pm);

    dim3 gg(CDIM / 128, NTOK / 128);
    gemm_tf32<<<gg, 256, SMEM_GEMM>>>(x, Wq, bq, Qp);
    gemm_tf32<<<gg, 256, SMEM_GEMM>>>(x, Wk, bk, Kp);
    gemm_tf32<<<gg, 256, SMEM_GEMM>>>(x, Wv, bv, Vp);

    dim3 rg((NTOK * 512) / 256, 3);
    rope_split<<<rg, 256>>>(Qp, Kp, Vp, cosT, sinT, QHL, KHL, VHL);

    attn_mma<<<dim3(NHEAD, NWIN_TOT), 256, SMEM_ATTN>>>(QHL, KHL, VHL, AOp);

    gemm_tf32<<<gg, 256, SMEM_GEMM>>>(AOp, Wo, bo, out);
}

// round 6
// speedup vs baseline: 3.2752x; 1.0404x over previous
#include <cuda_runtime.h>
#include <cuda_bf16.h>
#include <cstdint>

#define T_LEN 8192
#define BATCH 2
#define CDIM 1024
#define NHEAD 16
#define HDIM 64
#define WINSZ 256
#define NWIN_TOT 64
#define NTOK (BATCH * T_LEN)     // 16384

// ---------------- scratch ----------------------------------------------------
__device__ float g_Q[(size_t)NTOK * CDIM];
__device__ float g_K[(size_t)NTOK * CDIM];
__device__ float g_V[(size_t)NTOK * CDIM];
__device__ float g_AO[(size_t)NTOK * CDIM];       // attn output, tf32-rounded
__device__ float g_XT[(size_t)NTOK * CDIM];       // x, tf32-rounded
__device__ float g_WT[4][(size_t)CDIM * CDIM];    // weights, tf32-rounded
__device__ __nv_bfloat16 g_QHL[(size_t)NTOK * NHEAD * 128];
__device__ __nv_bfloat16 g_KHL[(size_t)NTOK * NHEAD * 128];
__device__ __nv_bfloat16 g_VHL[(size_t)NTOK * NHEAD * 128];
__device__ unsigned char g_attend[NWIN_TOT * 512];
__device__ int g_maskmode;

// ---------------- helpers ------------------------------------------------------
__device__ __forceinline__ uint32_t smem_u32(const void* p) {
    uint32_t a;
    asm("{ .reg .u64 t; cvta.to.shared.u64 t, %1; cvt.u32.u64 %0, t; }" : "=r"(a) : "l"(p));
    return a;
}
__device__ __forceinline__ void cp16(uint32_t dst, const void* src) {
    asm volatile("cp.async.cg.shared.global [%0], [%1], 16;" :: "r"(dst), "l"(src));
}
__device__ __forceinline__ void cp16z(uint32_t dst, const void* src, uint32_t sz) {
    asm volatile("cp.async.cg.shared.global [%0], [%1], 16, %2;" :: "r"(dst), "l"(src), "r"(sz));
}
__device__ __forceinline__ void cp_commit() { asm volatile("cp.async.commit_group;"); }
template <int N> __device__ __forceinline__ void cp_wait() {
    asm volatile("cp.async.wait_group %0;" :: "n"(N));
}
__device__ __forceinline__ void ldsm4(uint32_t (&r)[4], uint32_t addr) {
    asm volatile("ldmatrix.sync.aligned.m8n8.x4.shared.b16 {%0,%1,%2,%3}, [%4];"
                 : "=r"(r[0]), "=r"(r[1]), "=r"(r[2]), "=r"(r[3]) : "r"(addr));
}
__device__ __forceinline__ void ldsm4t(uint32_t (&r)[4], uint32_t addr) {
    asm volatile("ldmatrix.sync.aligned.m8n8.x4.trans.shared.b16 {%0,%1,%2,%3}, [%4];"
                 : "=r"(r[0]), "=r"(r[1]), "=r"(r[2]), "=r"(r[3]) : "r"(addr));
}
__device__ __forceinline__ void mma16816(float (&c)[4], const uint32_t (&a)[4],
                                         uint32_t b0, uint32_t b1) {
    asm volatile(
        "mma.sync.aligned.m16n8k16.row.col.f32.bf16.bf16.f32 "
        "{%0,%1,%2,%3}, {%4,%5,%6,%7}, {%8,%9}, {%0,%1,%2,%3};"
        : "+f"(c[0]), "+f"(c[1]), "+f"(c[2]), "+f"(c[3])
        : "r"(a[0]), "r"(a[1]), "r"(a[2]), "r"(a[3]), "r"(b0), "r"(b1));
}
__device__ __forceinline__ void mma_tf32(float (&c)[4], const uint32_t (&a)[4],
                                         uint32_t b0, uint32_t b1) {
    asm volatile(
        "mma.sync.aligned.m16n8k8.row.col.f32.tf32.tf32.f32 "
        "{%0,%1,%2,%3}, {%4,%5,%6,%7}, {%8,%9}, {%0,%1,%2,%3};"
        : "+f"(c[0]), "+f"(c[1]), "+f"(c[2]), "+f"(c[3])
        : "r"(a[0]), "r"(a[1]), "r"(a[2]), "r"(a[3]), "r"(b0), "r"(b1));
}
__device__ __forceinline__ uint32_t pack_bf16(float lo, float hi) {
    uint32_t r;
    asm("cvt.rn.bf16x2.f32 %0, %1, %2;" : "=r"(r) : "f"(hi), "f"(lo));
    return r;
}
__device__ __forceinline__ float bf_lo(uint32_t u) { return __uint_as_float(u << 16); }
__device__ __forceinline__ float bf_hi(uint32_t u) { return __uint_as_float(u & 0xffff0000u); }
__device__ __forceinline__ float rna_tf32(float f) {
    uint32_t r;
    asm("cvt.rna.tf32.f32 %0, %1;" : "=r"(r) : "f"(f));
    return __uint_as_float(r);
}
__device__ __forceinline__ uint32_t lds_u32(const char* smA, uint32_t off) {
    return *(const uint32_t*)(smA + off);
}

// ---------------- tf32 rounding pass ------------------------------------------
__global__ void round_tf32(const float* __restrict__ in, float* __restrict__ out) {
    int i = blockIdx.x * blockDim.x + threadIdx.x;
    float4 v = ((const float4*)in)[i];
    v.x = rna_tf32(v.x); v.y = rna_tf32(v.y);
    v.z = rna_tf32(v.z); v.w = rna_tf32(v.w);
    ((float4*)out)[i] = v;
}

// ---------------- TF32 GEMM: C[M,1024] = A[M,1024] @ W[1024,1024]^T + bias ----
// Inputs pre-rounded to tf32. Inner loop: pure LDS.32 + MMA.
#define GK 1024
#define GCH 32
#define GSTG 36864
#define GB_OFF 18432
#define SMEM_GEMM (3 * GSTG)

__device__ __forceinline__ void g_load_chunk(uint32_t stage, const float* Arow,
                                             const float* Brow, int kbase, int tid) {
#pragma unroll
    for (int i = 0; i < 4; i++) {
        int f = tid + i * 256;
        int rr = f >> 3, seg = f & 7;
        uint32_t dst = stage + (uint32_t)rr * 144 + (uint32_t)seg * 16;
        cp16(dst, Arow + (size_t)rr * GK + kbase + seg * 4);
        cp16(dst + GB_OFF, Brow + (size_t)rr * GK + kbase + seg * 4);
    }
}

__global__ void __launch_bounds__(256) gemm_tf32(const float* __restrict__ A,
        const float* __restrict__ W, const float* __restrict__ bias,
        float* __restrict__ C) {
    extern __shared__ char dsm[];
    int tid = threadIdx.x;
    int wid = tid >> 5, lane = tid & 31;
    int row0 = blockIdx.y * 128;
    int col0 = blockIdx.x * 128;
    int m0 = (wid & 3) * 32;
    int n0 = (wid >> 2) * 64;
    int gp = lane >> 2;
    int ci = lane & 3;

    const float* Arow = A + (size_t)row0 * GK;
    const float* Brow = W + (size_t)col0 * GK;

    uint32_t aBase[2], bBase[8];
#pragma unroll
    for (int mi = 0; mi < 2; mi++)
        aBase[mi] = (uint32_t)(m0 + mi * 16 + gp) * 144 + (uint32_t)ci * 4;
#pragma unroll
    for (int nt = 0; nt < 8; nt++)
        bBase[nt] = (uint32_t)GB_OFF + (uint32_t)(n0 + nt * 8 + gp) * 144 + (uint32_t)ci * 4;

    float acc[2][8][4];
#pragma unroll
    for (int mi = 0; mi < 2; mi++)
#pragma unroll
        for (int nt = 0; nt < 8; nt++)
#pragma unroll
            for (int j = 0; j < 4; j++) acc[mi][nt][j] = 0.0f;

    uint32_t sb = smem_u32(dsm);
    g_load_chunk(sb, Arow, Brow, 0, tid);
    cp_commit();
    g_load_chunk(sb + GSTG, Arow, Brow, 32, tid);
    cp_commit();

    for (int c = 0; c < GCH; c++) {
        if (c + 2 < GCH)
            g_load_chunk(sb + (uint32_t)((c + 2) % 3) * GSTG, Arow, Brow, (c + 2) * 32, tid);
        cp_commit();
        cp_wait<2>();
        __syncthreads();

        const char* stg = dsm + (size_t)(c % 3) * GSTG;
#pragma unroll
        for (int ks = 0; ks < 4; ks++) {
            uint32_t koff = (uint32_t)ks * 32;
            uint32_t b[8][2];
#pragma unroll
            for (int nt = 0; nt < 8; nt++) {
                b[nt][0] = lds_u32(stg, bBase[nt] + koff);
                b[nt][1] = lds_u32(stg, bBase[nt] + koff + 16);
            }
#pragma unroll
            for (int mi = 0; mi < 2; mi++) {
                uint32_t a[4];
                a[0] = lds_u32(stg, aBase[mi] + koff);
                a[1] = lds_u32(stg, aBase[mi] + 1152 + koff);
                a[2] = lds_u32(stg, aBase[mi] + koff + 16);
                a[3] = lds_u32(stg, aBase[mi] + 1152 + koff + 16);
#pragma unroll
                for (int nt = 0; nt < 8; nt++)
                    mma_tf32(acc[mi][nt], a, b[nt][0], b[nt][1]);
            }
        }
        __syncthreads();
    }

    int cl = ci * 2;
#pragma unroll
    for (int mi = 0; mi < 2; mi++) {
#pragma unroll
        for (int nt = 0; nt < 8; nt++) {
            int gcol = col0 + n0 + nt * 8 + cl;
            float b0 = bias[gcol], b1 = bias[gcol + 1];
            int r0 = row0 + m0 + mi * 16 + gp;
            float2 v0 = make_float2(acc[mi][nt][0] + b0, acc[mi][nt][1] + b1);
            float2 v1 = make_float2(acc[mi][nt][2] + b0, acc[mi][nt][3] + b1);
            *(float2*)(C + (size_t)r0 * CDIM + gcol) = v0;
            *(float2*)(C + (size_t)(r0 + 8) * CDIM + gcol) = v1;
        }
    }
}

// ---------------- mask dtype detection + attend mask -------------------------
__global__ void detect_mask(const unsigned int* __restrict__ m) {
    __shared__ int okf, oki;
    if (threadIdx.x == 0) { okf = 1; oki = 1; }
    __syncthreads();
    for (int i = threadIdx.x; i < 4096; i += blockDim.x) {
        unsigned int w = m[i];
        if (w != 0u && w != 0x3f800000u) okf = 0;
        if (w > 1u) oki = 0;
    }
    __syncthreads();
    if (threadIdx.x == 0) g_maskmode = okf ? 2 : (oki ? 1 : 0);
}

__global__ void build_attend(const void* __restrict__ pm) {
    int w = blockIdx.x;
    int b = w >> 5;
    int wi = w & 31;
    int j = threadIdx.x;
    int p = wi * WINSZ - 128 + j;
    int attend = 1;
    if ((unsigned)p < (unsigned)T_LEN) {
        int mm = g_maskmode;
        size_t im = (size_t)b * T_LEN + p;
        int v;
        if (mm == 0)      v = ((const unsigned char*)pm)[im] != 0;
        else if (mm == 1) v = ((const int*)pm)[im] != 0;
        else              v = ((const float*)pm)[im] != 0.0f;
        attend = !v;
    }
    __shared__ int allb;
    if (j == 0) allb = 1;
    __syncthreads();
    if (!attend) allb = 0;
    __syncthreads();
    if (j == 0 && allb) attend = 0;
    g_attend[w * 512 + j] = (unsigned char)attend;
}

// ---------------- fused rope + split (Q,K) / split (V) ------------------------
__global__ void rope_split(const float* __restrict__ Q, const float* __restrict__ K,
                           const float* __restrict__ V,
                           const float* __restrict__ cosT, const float* __restrict__ sinT,
                           __nv_bfloat16* __restrict__ QHL, __nv_bfloat16* __restrict__ KHL,
                           __nv_bfloat16* __restrict__ VHL) {
    int idx = blockIdx.x * blockDim.x + threadIdx.x;
    int z = blockIdx.y;
    const float* src = (z == 0) ? Q : ((z == 1) ? K : V);
    __nv_bfloat16* dst = (z == 0) ? QHL : ((z == 1) ? KHL : VHL);
    int token = idx >> 9;
    int r = idx & 511;
    int hh = r >> 5;
    int d = r & 31;
    int pos = token & (T_LEN - 1);
    size_t base = (size_t)token * CDIM + hh * HDIM;
    float a = src[base + d];
    float bv = src[base + d + 32];
    float o1, o2;
    if (z < 2) {
        float c1 = cosT[pos * HDIM + d], s1 = sinT[pos * HDIM + d];
        float c2 = cosT[pos * HDIM + d + 32], s2 = sinT[pos * HDIM + d + 32];
        o1 = a * c1 - bv * s1;
        o2 = bv * c2 + a * s2;
    } else { o1 = a; o2 = bv; }
    size_t ob = ((size_t)token * NHEAD + hh) * 128;
    __nv_bfloat16 h1 = __float2bfloat16_rn(o1);
    __nv_bfloat16 h2 = __float2bfloat16_rn(o2);
    dst[ob + d] = h1;
    dst[ob + d + 32] = h2;
    dst[ob + 64 + d] = __float2bfloat16_rn(o1 - __bfloat162float(h1));
    dst[ob + 96 + d] = __float2bfloat16_rn(o2 - __bfloat162float(h2));
}

// ---------------- tensor-core windowed attention ------------------------------
#define ATT_Q_LO 32768
#define ATT_STG 65536
#define ATT_BIAS 131072
#define SMEM_ATTN (1024 + 131072 + 256)

__device__ __forceinline__ void load_kv_chunk(uint32_t stg, const __nv_bfloat16* KHL,
        const __nv_bfloat16* VHL, int b, int h, int p0, int tid) {
#pragma unroll
    for (int i = 0; i < 2; i++) {
        int f = tid + i * 256;
        int r = f >> 3, seg = f & 7;
        int p = p0 + r;
        uint32_t ok = ((unsigned)p < (unsigned)T_LEN) ? 16u : 0u;
        int pc = (p < 0) ? 0 : ((p >= T_LEN) ? (T_LEN - 1) : p);
        const __nv_bfloat16* kk = KHL + (((size_t)(b * T_LEN + pc) * NHEAD + h) << 7) + seg * 8;
        const __nv_bfloat16* vv = VHL + (((size_t)(b * T_LEN + pc) * NHEAD + h) << 7) + seg * 8;
        uint32_t sw = (uint32_t)r * 128 + (uint32_t)(((seg ^ (r & 7)) << 4));
        cp16z(stg + sw, kk, ok);
        cp16z(stg + 8192 + sw, kk + 64, ok);
        cp16z(stg + 16384 + sw, vv, ok);
        cp16z(stg + 24576 + sw, vv + 64, ok);
    }
}

__global__ void __launch_bounds__(256) attn_mma(
        const __nv_bfloat16* __restrict__ QHL, const __nv_bfloat16* __restrict__ KHL,
        const __nv_bfloat16* __restrict__ VHL, float* __restrict__ AO) {
    extern __shared__ char sm[];
    char* smA = (char*)(((uintptr_t)sm + 1023) & ~(uintptr_t)1023);
    uint32_t sb = smem_u32(smA);
    float* biasP = (float*)(smA + ATT_BIAS);

    int h = blockIdx.x, w = blockIdx.y;
    int b = w >> 5, wi = w & 31;
    int tid = threadIdx.x, wid = tid >> 5, lane = tid & 31;
    int w0 = wid * 32;

    int rA = (lane & 7) + ((lane >> 3) & 1) * 8;
    int ksegA = lane >> 4;
    int rB = (lane & 7) + ((lane >> 4) << 3);
    int ksegB = (lane >> 3) & 1;
    int krV = (lane & 7) + ((lane >> 4) << 3);
    int nsegV = (lane >> 3) & 1;

#pragma unroll
    for (int i = 0; i < 8; i++) {
        int f = tid + i * 256;
        int r = f >> 3, seg = f & 7;
        const __nv_bfloat16* q = QHL + (((size_t)(b * T_LEN + wi * 256 + r) * NHEAD + h) << 7)
                                 + seg * 8;
        uint32_t sw = (uint32_t)r * 128 + (uint32_t)(((seg ^ (r & 7)) << 4));
        cp16(sb + sw, q);
        cp16(sb + ATT_Q_LO + sw, q + 64);
    }
    load_kv_chunk(sb + ATT_STG, KHL, VHL, b, h, wi * 256 - 128, tid);
    cp_commit();
    load_kv_chunk(sb + ATT_STG + 32768, KHL, VHL, b, h, wi * 256 - 64, tid);
    cp_commit();

    float O[2][8][4];
#pragma unroll
    for (int mi = 0; mi < 2; mi++)
#pragma unroll
        for (int nt = 0; nt < 8; nt++)
#pragma unroll
            for (int j = 0; j < 4; j++) O[mi][nt][j] = 0.0f;
    float mrow[4] = {-3e38f, -3e38f, -3e38f, -3e38f};
    float lrow[4] = {0.f, 0.f, 0.f, 0.f};

    for (int c = 0; c < 8; c++) {
        if (c < 6) { cp_wait<1>(); } else { cp_wait<0>(); }
        if (tid < 64)
            biasP[tid] = g_attend[w * 512 + c * 64 + tid] ? 0.0f : -1e30f;
        __syncthreads();

        uint32_t stg = sb + ATT_STG + (uint32_t)(c & 1) * 32768u;

        float S[2][8][4];
#pragma unroll
        for (int mi = 0; mi < 2; mi++)
#pragma unroll
            for (int nt = 0; nt < 8; nt++)
#pragma unroll
                for (int j = 0; j < 4; j++) S[mi][nt][j] = 0.0f;

#pragma unroll
        for (int pass = 0; pass < 3; pass++) {
            uint32_t qoff = (pass == 2) ? (uint32_t)ATT_Q_LO : 0u;
            uint32_t koff = (pass == 1) ? 8192u : 0u;
#pragma unroll
            for (int step = 0; step < 4; step++) {
                uint32_t kb[4][4];
#pragma unroll
                for (int g = 0; g < 4; g++) {
                    int row = g * 16 + rB;
                    ldsm4(kb[g], stg + koff + (uint32_t)row * 128
                          + (uint32_t)(((step * 2 + ksegB) ^ (row & 7)) << 4));
                }
#pragma unroll
                for (int mi = 0; mi < 2; mi++) {
                    int rowQ = w0 + mi * 16 + rA;
                    uint32_t qf[4];
                    ldsm4(qf, sb + qoff + (uint32_t)rowQ * 128
                          + (uint32_t)(((step * 2 + ksegA) ^ (rowQ & 7)) << 4));
#pragma unroll
                    for (int nt = 0; nt < 8; nt++)
                        mma16816(S[mi][nt], qf, kb[nt >> 1][(nt & 1) * 2],
                                 kb[nt >> 1][(nt & 1) * 2 + 1]);
                }
            }
        }

        float2 bias[8];
#pragma unroll
        for (int nt = 0; nt < 8; nt++)
            bias[nt] = *(float2*)&biasP[nt * 8 + 2 * (lane & 3)];
#pragma unroll
        for (int mi = 0; mi < 2; mi++)
#pragma unroll
            for (int nt = 0; nt < 8; nt++) {
                S[mi][nt][0] = fmaf(S[mi][nt][0], 0.125f, bias[nt].x);
                S[mi][nt][1] = fmaf(S[mi][nt][1], 0.125f, bias[nt].y);
                S[mi][nt][2] = fmaf(S[mi][nt][2], 0.125f, bias[nt].x);
                S[mi][nt][3] = fmaf(S[mi][nt][3], 0.125f, bias[nt].y);
            }
#pragma unroll
        for (int mi = 0; mi < 2; mi++)
#pragma unroll
            for (int hh = 0; hh < 2; hh++) {
                int s = mi * 2 + hh;
                float rm = -3e38f;
#pragma unroll
                for (int nt = 0; nt < 8; nt++)
                    rm = fmaxf(rm, fmaxf(S[mi][nt][hh * 2], S[mi][nt][hh * 2 + 1]));
                rm = fmaxf(rm, __shfl_xor_sync(0xffffffffu, rm, 1));
                rm = fmaxf(rm, __shfl_xor_sync(0xffffffffu, rm, 2));
                float mn = fmaxf(mrow[s], rm);
                float sc = __expf(mrow[s] - mn);
                mrow[s] = mn;
                float ls = 0.0f;
#pragma unroll
                for (int nt = 0; nt < 8; nt++) {
                    float p0 = __expf(S[mi][nt][hh * 2] - mn);
                    float p1 = __expf(S[mi][nt][hh * 2 + 1] - mn);
                    S[mi][nt][hh * 2] = p0;
                    S[mi][nt][hh * 2 + 1] = p1;
                    ls += p0 + p1;
                    O[mi][nt][hh * 2] *= sc;
                    O[mi][nt][hh * 2 + 1] *= sc;
                }
                lrow[s] = lrow[s] * sc + ls;
            }

#pragma unroll
        for (int step = 0; step < 4; step++) {
            uint32_t ah[2][4], al[2][4];
#pragma unroll
            for (int mi = 0; mi < 2; mi++)
#pragma unroll
                for (int t2 = 0; t2 < 2; t2++) {
                    float p0 = S[mi][2 * step + t2][0], p1 = S[mi][2 * step + t2][1];
                    float p2 = S[mi][2 * step + t2][2], p3 = S[mi][2 * step + t2][3];
                    uint32_t hA = pack_bf16(p0, p1);
                    uint32_t hB = pack_bf16(p2, p3);
                    ah[mi][t2 * 2] = hA;
                    ah[mi][t2 * 2 + 1] = hB;
                    al[mi][t2 * 2] = pack_bf16(p0 - bf_lo(hA), p1 - bf_hi(hA));
                    al[mi][t2 * 2 + 1] = pack_bf16(p2 - bf_lo(hB), p3 - bf_hi(hB));
                }
            uint32_t vb[4][4];
#pragma unroll
            for (int g = 0; g < 4; g++) {
                int vrow = step * 16 + krV;
                int seg = g * 2 + nsegV;
                ldsm4t(vb[g], stg + 16384u + (uint32_t)vrow * 128
                       + (uint32_t)(((seg ^ (vrow & 7)) << 4)));
            }
#pragma unroll
            for (int mi = 0; mi < 2; mi++)
#pragma unroll
                for (int nt = 0; nt < 8; nt++) {
                    uint32_t b0 = vb[nt >> 1][nt & 1], b1 = vb[nt >> 1][(nt & 1) + 2];
                    mma16816(O[mi][nt], ah[mi], b0, b1);
                    mma16816(O[mi][nt], al[mi], b0, b1);
                }
#pragma unroll
            for (int g = 0; g < 4; g++) {
                int vrow = step * 16 + krV;
                int seg = g * 2 + nsegV;
                ldsm4t(vb[g], stg + 24576u + (uint32_t)vrow * 128
                       + (uint32_t)(((seg ^ (vrow & 7)) << 4)));
            }
#pragma unroll
            for (int mi = 0; mi < 2; mi++)
#pragma unroll
                for (int nt = 0; nt < 8; nt++)
                    mma16816(O[mi][nt], ah[mi], vb[nt >> 1][nt & 1],
                             vb[nt >> 1][(nt & 1) + 2]);
        }

        __syncthreads();
        if (c + 2 < 8) {
            load_kv_chunk(sb + ATT_STG + (uint32_t)(c & 1) * 32768u, KHL, VHL, b, h,
                          wi * 256 - 128 + (c + 2) * 64, tid);
            cp_commit();
        }
    }

#pragma unroll
    for (int s = 0; s < 4; s++) {
        lrow[s] += __shfl_xor_sync(0xffffffffu, lrow[s], 1);
        lrow[s] += __shfl_xor_sync(0xffffffffu, lrow[s], 2);
        lrow[s] = 1.0f / lrow[s];
    }
    int rr = lane >> 2, cc = 2 * (lane & 3);
#pragma unroll
    for (int mi = 0; mi < 2; mi++)
#pragma unroll
        for (int nt = 0; nt < 8; nt++) {
            int tok0 = b * T_LEN + wi * 256 + w0 + mi * 16 + rr;
            int col = h * 64 + nt * 8 + cc;
            // write AO pre-rounded to tf32 so the O-projection GEMM needs no cvt
            float2 v0 = make_float2(rna_tf32(O[mi][nt][0] * lrow[mi * 2]),
                                    rna_tf32(O[mi][nt][1] * lrow[mi * 2]));
            float2 v1 = make_float2(rna_tf32(O[mi][nt][2] * lrow[mi * 2 + 1]),
                                    rna_tf32(O[mi][nt][3] * lrow[mi * 2 + 1]));
            *(float2*)(AO + (size_t)tok0 * CDIM + col) = v0;
            *(float2*)(AO + (size_t)(tok0 + 8) * CDIM + col) = v1;
        }
}

// ---------------- launch --------------------------------------------------------
extern "C" void kernel_launch(void* const* d_in, const int* in_sizes, int n_in,
                              void* d_out, int out_size) {
    const float* x    = (const float*)d_in[0];
    const void*  pm   = d_in[1];
    const float* cosT = (const float*)d_in[2];
    const float* sinT = (const float*)d_in[3];
    const float* Wq   = (const float*)d_in[4];
    const float* bq   = (const float*)d_in[5];
    const float* Wk   = (const float*)d_in[6];
    const float* bk   = (const float*)d_in[7];
    const float* Wv   = (const float*)d_in[8];
    const float* bv   = (const float*)d_in[9];
    const float* Wo   = (const float*)d_in[10];
    const float* bo   = (const float*)d_in[11];
    float* out = (float*)d_out;

    float *Qp, *Kp, *Vp, *AOp, *XT, *WT;
    __nv_bfloat16 *QHL, *KHL, *VHL;
    cudaGetSymbolAddress((void**)&Qp, g_Q);
    cudaGetSymbolAddress((void**)&Kp, g_K);
    cudaGetSymbolAddress((void**)&Vp, g_V);
    cudaGetSymbolAddress((void**)&AOp, g_AO);
    cudaGetSymbolAddress((void**)&XT, g_XT);
    cudaGetSymbolAddress((void**)&WT, g_WT);
    cudaGetSymbolAddress((void**)&QHL, g_QHL);
    cudaGetSymbolAddress((void**)&KHL, g_KHL);
    cudaGetSymbolAddress((void**)&VHL, g_VHL);

    cudaFuncSetAttribute(gemm_tf32, cudaFuncAttributeMaxDynamicSharedMemorySize, SMEM_GEMM);
    cudaFuncSetAttribute(attn_mma, cudaFuncAttributeMaxDynamicSharedMemorySize, SMEM_ATTN);

    detect_mask<<<1, 256>>>((const unsigned int*)pm);
    build_attend<<<NWIN_TOT, 512>>>(pm);

    // pre-round inputs to tf32 (one pass each)
    round_tf32<<<NTOK * CDIM / 1024, 256>>>(x, XT);
    round_tf32<<<CDIM * CDIM / 1024, 256>>>(Wq, WT + 0 * (size_t)CDIM * CDIM);
    round_tf32<<<CDIM * CDIM / 1024, 256>>>(Wk, WT + 1 * (size_t)CDIM * CDIM);
    round_tf32<<<CDIM * CDIM / 1024, 256>>>(Wv, WT + 2 * (size_t)CDIM * CDIM);
    round_tf32<<<CDIM * CDIM / 1024, 256>>>(Wo, WT + 3 * (size_t)CDIM * CDIM);

    dim3 gg(CDIM / 128, NTOK / 128);
    gemm_tf32<<<gg, 256, SMEM_GEMM>>>(XT, WT + 0 * (size_t)CDIM * CDIM, bq, Qp);
    gemm_tf32<<<gg, 256, SMEM_GEMM>>>(XT, WT + 1 * (size_t)CDIM * CDIM, bk, Kp);
    gemm_tf32<<<gg, 256, SMEM_GEMM>>>(XT, WT + 2 * (size_t)CDIM * CDIM, bv, Vp);

    dim3 rg((NTOK * 512) / 256, 3);
    rope_split<<<rg, 256>>>(Qp, Kp, Vp, cosT, sinT, QHL, KHL, VHL);

    attn_mma<<<dim3(NHEAD, NWIN_TOT), 256, SMEM_ATTN>>>(QHL, KHL, VHL, AOp);

    gemm_tf32<<<gg, 256, SMEM_GEMM>>>(AOp, WT + 3 * (size_t)CDIM * CDIM, bo, out);
}